// round 13
// baseline (speedup 1.0000x reference)
#include <cuda_runtime.h>
#include <cuda_bf16.h>
#include <cstdint>
#include <math.h>

#define C     64
#define S     512
#define P     4096
#define NB    32
#define NTOK  (NB * P)          // 131072
#define TOK   128               // tokens per block
#define TPB   256
#define CAND  16

// output layout (float32, tuple flattened in order)
#define OFF_LOSS 0
#define OFF_IDX  1
#define OFF_OUT  (OFF_IDX + NTOK)
#define OFF_NCB  (OFF_OUT + NTOK * C)
#define OFF_CS   (OFF_NCB + S * C)
#define OFF_EW   (OFF_CS + S)

// smem byte layout
#define SMB_TOK   0              // fp32 tok[C][TOK]        32768
#define SMB_A     32768          // bf16 A[128][64]         16384 } union: fp32 xq[C][TOK]
#define SMB_B     49152          // bf16 B[256][64] x2 subtiles 32768 }
#define SMB_SCN   81920          // fp32 [S]                 2048
#define SMB_STN   83968          // fp32 [TOK]                512
#define SMB_GMIN  84480          // u32  [TOK] ordered keys   512
#define SMB_THR   84992          // fp32 [TOK]                512
#define SMB_SBI   85504          // int  [TOK]                512
#define SMB_CND   86016          // int  [TOK][CAND]         8192
#define SMB_CNT   94208          // int  [TOK]                512
#define SMB_PBV   94720          // fp32 [TPB]               1024
#define SMB_PBI   95744          // int  [TPB]               1024
#define SMB_RED   96768          // fp32 [8]                   32
#define SMB_SMAX  96800          // u32                         4
#define SMEM_BYTES 96832

#define SW128(b) ((b) ^ (((b) >> 3) & 0x70))

// ---------------- device scratch ----------------
__device__ float g_counts[S];
__device__ float g_dw[S * C];
__device__ float g_cnorm[S];
__device__ float g_loss;
__device__ uint4 g_cbBf[S * C * 2 / 16];   // bf16 codebook [s][c], 128B rows

// ---------------- helpers ----------------
__device__ __forceinline__ unsigned smem_u32(const void* p) {
    unsigned a;
    asm("{ .reg .u64 t; cvta.to.shared.u64 t, %1; cvt.u32.u64 %0, t; }" : "=r"(a) : "l"(p));
    return a;
}
__device__ __forceinline__ void ldmx4(unsigned& r0, unsigned& r1, unsigned& r2, unsigned& r3,
                                      unsigned addr) {
    asm volatile("ldmatrix.sync.aligned.m8n8.x4.shared.b16 {%0,%1,%2,%3}, [%4];"
                 : "=r"(r0), "=r"(r1), "=r"(r2), "=r"(r3) : "r"(addr));
}
__device__ __forceinline__ void ldmx2(unsigned& r0, unsigned& r1, unsigned addr) {
    asm volatile("ldmatrix.sync.aligned.m8n8.x2.shared.b16 {%0,%1}, [%2];"
                 : "=r"(r0), "=r"(r1) : "r"(addr));
}
__device__ __forceinline__ void mma_bf16(float* d, const unsigned* a, const unsigned* b) {
    asm volatile("mma.sync.aligned.m16n8k16.row.col.f32.bf16.bf16.f32 "
                 "{%0,%1,%2,%3}, {%4,%5,%6,%7}, {%8,%9}, {%0,%1,%2,%3};"
                 : "+f"(d[0]), "+f"(d[1]), "+f"(d[2]), "+f"(d[3])
                 : "r"(a[0]), "r"(a[1]), "r"(a[2]), "r"(a[3]), "r"(b[0]), "r"(b[1]));
}
// ordered-int encode/decode for float atomicMin over any-sign floats
__device__ __forceinline__ unsigned fkey(float f) {
    unsigned b = __float_as_uint(f);
    return b ^ ((b & 0x80000000u) ? 0xffffffffu : 0x80000000u);
}
__device__ __forceinline__ float fdec(unsigned k) {
    unsigned b = (k & 0x80000000u) ? (k ^ 0x80000000u) : ~k;
    return __uint_as_float(b);
}

// exact reference-lattice distance for (token t, code s)
__device__ __forceinline__ float rescore_one(const float* tokp, int t, int s, float A,
                                             const float* scn, const float* codebook) {
    const float4* cr = (const float4*)(codebook + s * C);
    float B = 0.f;
    #pragma unroll
    for (int q = 0; q < 16; q++) {
        float4 w = __ldg(cr + q);
        int c = q * 4;
        B = fmaf(tokp[(c + 0) * TOK + t], w.x, B);
        B = fmaf(tokp[(c + 1) * TOK + t], w.y, B);
        B = fmaf(tokp[(c + 2) * TOK + t], w.z, B);
        B = fmaf(tokp[(c + 3) * TOK + t], w.w, B);
    }
    return __fadd_rn(__fmaf_rn(-2.0f, B, A), scn[s]);
}

// ---------------- prep ----------------
__global__ void vq_prep_kernel(const float* __restrict__ codebook) {
    int gid = blockIdx.x * blockDim.x + threadIdx.x;
    if (gid < S * C / 4) {
        float4 v = ((const float4*)codebook)[gid];
        __nv_bfloat162 q0 = __floats2bfloat162_rn(v.x, v.y);
        __nv_bfloat162 q1 = __floats2bfloat162_rn(v.z, v.w);
        uint2 w;
        w.x = *(unsigned*)&q0; w.y = *(unsigned*)&q1;
        ((uint2*)g_cbBf)[gid] = w;
        ((float4*)g_dw)[gid] = make_float4(0.f, 0.f, 0.f, 0.f);
    }
    int r = gid - S * C / 4;
    if (r >= 0 && r < S) {
        const float* row = codebook + r * C;
        float acc = 0.f;
        #pragma unroll
        for (int c = 0; c < C; c++)
            acc = __fadd_rn(acc, __fmul_rn(row[c], row[c]));
        g_cnorm[r] = acc;
        g_counts[r] = 0.f;
        if (r == 0) g_loss = 0.f;
    }
}

// ---------------- main ----------------
__global__ void __launch_bounds__(TPB, 2)
vq_main_kernel(const float* __restrict__ x,
               const float* __restrict__ codebook,
               float* __restrict__ outp) {
    extern __shared__ char smc[];
    float* tok  = (float*)(smc + SMB_TOK);
    float* scr  = (float*)(smc + SMB_A);     // fp32 view of A/B union (xq tile)
    float* scn  = (float*)(smc + SMB_SCN);
    float* stn2 = (float*)(smc + SMB_STN);
    unsigned* sgmin = (unsigned*)(smc + SMB_GMIN);
    float* sthr = (float*)(smc + SMB_THR);
    int*   sbi  = (int*)(smc + SMB_SBI);
    int*   scand= (int*)(smc + SMB_CND);
    int*   scnt = (int*)(smc + SMB_CNT);
    float* pbv  = (float*)(smc + SMB_PBV);
    int*   pbi  = (int*)(smc + SMB_PBI);
    float* sred = (float*)(smc + SMB_RED);
    unsigned* smaxb = (unsigned*)(smc + SMB_SMAX);

    const unsigned sbase = smem_u32(smc);
    const int tid  = threadIdx.x;
    const int w    = tid >> 5;
    const int lane = tid & 31;
    const int tw   = w & 3;        // token tile (32 tokens)
    const int sw   = w >> 2;       // code half within each round
    const int b    = blockIdx.x;
    const int n    = b >> 5;
    const int p0   = (b & 31) * TOK;
    const float* xb = x + (size_t)n * C * P + p0;

    if (tid == 0) *smaxb = 0;
    if (tid < TOK) { scnt[tid] = 0; sgmin[tid] = 0xffffffffu; }
    __syncthreads();

    // code norms + block max
    {
        float mx = 0.f;
        for (int i = tid; i < S; i += TPB) {
            float v = g_cnorm[i];
            scn[i] = v;
            mx = fmaxf(mx, v);
        }
        atomicMax((int*)smaxb, __float_as_int(mx));
    }

    // x tile fp32 [c][t]
    for (int v = tid; v < C * TOK / 4; v += TPB) {
        int c = v >> 5, q = v & 31;
        *(float4*)(tok + c * TOK + q * 4) = *(const float4*)(xb + c * P + q * 4);
    }
    __syncthreads();

    // token norms (reference rounding)
    if (tid < TOK) {
        float a = 0.f;
        #pragma unroll
        for (int c = 0; c < C; c++) {
            float v = tok[c * TOK + tid];
            a = __fadd_rn(a, __fmul_rn(v, v));
        }
        stn2[tid] = a;
    }

    // convert A tile to bf16 [t][k], 128B SW128 rows
    {
        int t = tid >> 1, half = tid & 1, k0 = half * 32;
        #pragma unroll
        for (int q = 0; q < 4; q++) {
            unsigned u[4];
            #pragma unroll
            for (int j = 0; j < 4; j++) {
                int k = k0 + q * 8 + j * 2;
                __nv_bfloat162 pr = __floats2bfloat162_rn(tok[k * TOK + t], tok[(k + 1) * TOK + t]);
                u[j] = *(unsigned*)&pr;
            }
            unsigned byte = (unsigned)(t * 128 + half * 64 + q * 16);
            *(uint4*)(smc + SMB_A + SW128(byte)) = make_uint4(u[0], u[1], u[2], u[3]);
        }
    }
    __syncthreads();

    // A fragments: 2 m-tiles (32 tokens) x 64 k per warp
    unsigned afr[2][4][4];
    #pragma unroll
    for (int mi = 0; mi < 2; mi++)
        #pragma unroll
        for (int kc = 0; kc < 4; kc++) {
            unsigned byte = (unsigned)((tw * 32 + mi * 16 + (lane & 15)) * 128 + kc * 32 + (lane >> 4) * 16);
            ldmx4(afr[mi][kc][0], afr[mi][kc][1], afr[mi][kc][2], afr[mi][kc][3],
                  sbase + SMB_A + SW128(byte));
        }

    // hoisted B-fragment addresses (SW128 xor is jt-invariant; step +1024B/jt)
    unsigned baddr[4];
    #pragma unroll
    for (int kc = 0; kc < 4; kc++) {
        unsigned byte = (unsigned)(sw * 16384 + (lane & 7) * 128 + kc * 32 + ((lane >> 3) & 1) * 16);
        baddr[kc] = sbase + SMB_B + SW128(byte);
    }

    const int g  = lane >> 2;      // fragment row group
    const int qq = lane & 3;       // fragment col pair
    const int t0 = tw * 32 + g;    // token rows: t0, t0+8, t0+16, t0+24
    const float smax = __int_as_float(*(int*)smaxb);

    // ---- scan 1 (SUBSET, codes 0..255): gmin over-estimate per token ----
    // thr = gmin_subset + marg >= gmin + marg, so the scan-2 capture remains
    // a provable superset of the exact argmin; looser thr only adds candidates.
    {
        float rmin[4] = {3.4e38f, 3.4e38f, 3.4e38f, 3.4e38f};
        for (int task = tid; task < 512; task += TPB) {
            int row = task >> 1, half = task & 1;
            const uint4* src = g_cbBf + row * 8 + half * 4;
            #pragma unroll
            for (int q = 0; q < 4; q++) {
                unsigned byte = (unsigned)(row * 128 + half * 64 + q * 16);
                *(uint4*)(smc + SMB_B + SW128(byte)) = src[q];
            }
        }
        __syncthreads();
        #pragma unroll 2
        for (int jt = 0; jt < 16; jt++) {
            unsigned bfr[4][2];
            #pragma unroll
            for (int kc = 0; kc < 4; kc++)
                ldmx2(bfr[kc][0], bfr[kc][1], baddr[kc] + (unsigned)jt * 1024);
            float d0A[4] = {0,0,0,0}, d0B[4] = {0,0,0,0};
            float d1A[4] = {0,0,0,0}, d1B[4] = {0,0,0,0};
            mma_bf16(d0A, afr[0][0], bfr[0]);
            mma_bf16(d1A, afr[1][0], bfr[0]);
            mma_bf16(d0B, afr[0][1], bfr[1]);
            mma_bf16(d1B, afr[1][1], bfr[1]);
            mma_bf16(d0A, afr[0][2], bfr[2]);
            mma_bf16(d1A, afr[1][2], bfr[2]);
            mma_bf16(d0B, afr[0][3], bfr[3]);
            mma_bf16(d1B, afr[1][3], bfr[3]);

            int s0 = sw * 128 + jt * 8 + qq * 2;
            float cn0 = scn[s0], cn1 = scn[s0 + 1];
            rmin[0] = fminf(rmin[0], fminf(__fmaf_rn(-2.f, d0A[0] + d0B[0], cn0),
                                           __fmaf_rn(-2.f, d0A[1] + d0B[1], cn1)));
            rmin[1] = fminf(rmin[1], fminf(__fmaf_rn(-2.f, d0A[2] + d0B[2], cn0),
                                           __fmaf_rn(-2.f, d0A[3] + d0B[3], cn1)));
            rmin[2] = fminf(rmin[2], fminf(__fmaf_rn(-2.f, d1A[0] + d1B[0], cn0),
                                           __fmaf_rn(-2.f, d1A[1] + d1B[1], cn1)));
            rmin[3] = fminf(rmin[3], fminf(__fmaf_rn(-2.f, d1A[2] + d1B[2], cn0),
                                           __fmaf_rn(-2.f, d1A[3] + d1B[3], cn1)));
        }
        __syncthreads();
        #pragma unroll
        for (int i = 0; i < 4; i++) {
            rmin[i] = fminf(rmin[i], __shfl_xor_sync(0xffffffffu, rmin[i], 1));
            rmin[i] = fminf(rmin[i], __shfl_xor_sync(0xffffffffu, rmin[i], 2));
        }
        if (qq == 0) {
            atomicMin(&sgmin[t0],      fkey(rmin[0]));
            atomicMin(&sgmin[t0 + 8],  fkey(rmin[1]));
            atomicMin(&sgmin[t0 + 16], fkey(rmin[2]));
            atomicMin(&sgmin[t0 + 24], fkey(rmin[3]));
        }
    }
    __syncthreads();

    // capture thresholds: subset gmin + margin (2x bf16 dot error bound + 25%)
    if (tid < TOK)
        sthr[tid] = fdec(sgmin[tid]) + 1.25f * 0.03125f * sqrtf(stn2[tid] * smax) + 1e-5f;
    __syncthreads();

    // ---- scan 2: full 512 codes, capture candidates vs threshold ----
    {
        const float thr0 = sthr[t0], thr1 = sthr[t0 + 8], thr2 = sthr[t0 + 16], thr3 = sthr[t0 + 24];
        for (int r = 0; r < 2; r++) {
            for (int task = tid; task < 512; task += TPB) {
                int row = task >> 1, half = task & 1;
                const uint4* src = g_cbBf + (r * 256 + row) * 8 + half * 4;
                #pragma unroll
                for (int q = 0; q < 4; q++) {
                    unsigned byte = (unsigned)(row * 128 + half * 64 + q * 16);
                    *(uint4*)(smc + SMB_B + SW128(byte)) = src[q];
                }
            }
            __syncthreads();
            #pragma unroll 2
            for (int jt = 0; jt < 16; jt++) {
                unsigned bfr[4][2];
                #pragma unroll
                for (int kc = 0; kc < 4; kc++)
                    ldmx2(bfr[kc][0], bfr[kc][1], baddr[kc] + (unsigned)jt * 1024);
                float d0A[4] = {0,0,0,0}, d0B[4] = {0,0,0,0};
                float d1A[4] = {0,0,0,0}, d1B[4] = {0,0,0,0};
                mma_bf16(d0A, afr[0][0], bfr[0]);
                mma_bf16(d1A, afr[1][0], bfr[0]);
                mma_bf16(d0B, afr[0][1], bfr[1]);
                mma_bf16(d1B, afr[1][1], bfr[1]);
                mma_bf16(d0A, afr[0][2], bfr[2]);
                mma_bf16(d1A, afr[1][2], bfr[2]);
                mma_bf16(d0B, afr[0][3], bfr[3]);
                mma_bf16(d1B, afr[1][3], bfr[3]);

                int s0 = r * 256 + sw * 128 + jt * 8 + qq * 2;
                float cn0 = scn[s0], cn1 = scn[s0 + 1];
                float v;
                v = __fmaf_rn(-2.f, d0A[0] + d0B[0], cn0);
                if (v <= thr0) { int sl = atomicAdd(&scnt[t0], 1); if (sl < CAND) scand[t0 * CAND + sl] = s0; }
                v = __fmaf_rn(-2.f, d0A[1] + d0B[1], cn1);
                if (v <= thr0) { int sl = atomicAdd(&scnt[t0], 1); if (sl < CAND) scand[t0 * CAND + sl] = s0 + 1; }
                v = __fmaf_rn(-2.f, d0A[2] + d0B[2], cn0);
                if (v <= thr1) { int sl = atomicAdd(&scnt[t0 + 8], 1); if (sl < CAND) scand[(t0 + 8) * CAND + sl] = s0; }
                v = __fmaf_rn(-2.f, d0A[3] + d0B[3], cn1);
                if (v <= thr1) { int sl = atomicAdd(&scnt[t0 + 8], 1); if (sl < CAND) scand[(t0 + 8) * CAND + sl] = s0 + 1; }
                v = __fmaf_rn(-2.f, d1A[0] + d1B[0], cn0);
                if (v <= thr2) { int sl = atomicAdd(&scnt[t0 + 16], 1); if (sl < CAND) scand[(t0 + 16) * CAND + sl] = s0; }
                v = __fmaf_rn(-2.f, d1A[1] + d1B[1], cn1);
                if (v <= thr2) { int sl = atomicAdd(&scnt[t0 + 16], 1); if (sl < CAND) scand[(t0 + 16) * CAND + sl] = s0 + 1; }
                v = __fmaf_rn(-2.f, d1A[2] + d1B[2], cn0);
                if (v <= thr3) { int sl = atomicAdd(&scnt[t0 + 24], 1); if (sl < CAND) scand[(t0 + 24) * CAND + sl] = s0; }
                v = __fmaf_rn(-2.f, d1A[3] + d1B[3], cn1);
                if (v <= thr3) { int sl = atomicAdd(&scnt[t0 + 24], 1); if (sl < CAND) scand[(t0 + 24) * CAND + sl] = s0 + 1; }
            }
            __syncthreads();
        }
    }

    // ---- exact rescore (2 threads per token) ----
    {
        int t = tid & 127;
        int half = tid >> 7;
        float A = stn2[t];
        float bestd = 3.4e38f;
        int bests = 1 << 30;
        int cnt = scnt[t];
        if (cnt <= CAND) {
            for (int i = half; i < cnt; i += 2) {
                int s = scand[t * CAND + i];
                float d = rescore_one(tok, t, s, A, scn, codebook);
                if (d < bestd || (d == bestd && s < bests)) { bestd = d; bests = s; }
            }
        } else {
            for (int s = half; s < S; s += 2) {
                float d = rescore_one(tok, t, s, A, scn, codebook);
                if (d < bestd || (d == bestd && s < bests)) { bestd = d; bests = s; }
            }
        }
        pbv[tid] = bestd;
        pbi[tid] = bests;
    }
    __syncthreads();
    if (tid < TOK) {
        float d1 = pbv[tid];       int s1 = pbi[tid];
        float d2 = pbv[tid + 128]; int s2 = pbi[tid + 128];
        int bs = (d2 < d1 || (d2 == d1 && s2 < s1)) ? s2 : s1;
        sbi[tid] = bs;
        outp[OFF_IDX + (size_t)n * P + p0 + tid] = (float)bs;
        atomicAdd(&g_counts[bs], 1.0f);
    }
    __syncthreads();

    // gather xq into scr[c][t] (overwrites A/B tiles) + dw scatter
    {
        int t = tid >> 1, c0 = (tid & 1) * 32;
        int sdx = sbi[t];
        const float4* crow = (const float4*)(codebook + sdx * C + c0);
        #pragma unroll
        for (int q = 0; q < 8; q++) {
            float4 v = crow[q];
            int c = c0 + q * 4;
            scr[(c + 0) * TOK + t] = v.x;
            scr[(c + 1) * TOK + t] = v.y;
            scr[(c + 2) * TOK + t] = v.z;
            scr[(c + 3) * TOK + t] = v.w;
        }
        float* dwrow = g_dw + sdx * C + c0;
        #pragma unroll 8
        for (int j = 0; j < 32; j++)
            atomicAdd(&dwrow[j], tok[(c0 + j) * TOK + t]);
    }
    __syncthreads();

    // straight-through out + commitment loss
    float lsum = 0.f;
    float* ob = outp + OFF_OUT + (size_t)n * C * P + p0;
    for (int v = tid; v < C * TOK; v += TPB) {
        int c = v >> 7, t = v & 127;
        float xv = tok[c * TOK + t];
        float qv = scr[c * TOK + t];
        ob[c * P + t] = xv + (qv - xv);
        float dd = xv - qv;
        lsum = fmaf(dd, dd, lsum);
    }
    #pragma unroll
    for (int d = 16; d >= 1; d >>= 1) lsum += __shfl_xor_sync(0xffffffffu, lsum, d);
    if (lane == 0) sred[w] = lsum;
    __syncthreads();
    if (tid == 0) {
        float tot = 0.f;
        #pragma unroll
        for (int q = 0; q < TPB / 32; q++) tot += sred[q];
        atomicAdd(&g_loss, tot);
    }
}

// ---------------- finalize: 64 blocks, each redundantly reduces nsum ----------------
__global__ void vq_finalize_kernel(const float* __restrict__ ema_w,
                                   const float* __restrict__ cluster_size,
                                   const int* __restrict__ steps_p,
                                   float* __restrict__ outp) {
    __shared__ float sred[S];
    int t = threadIdx.x;          // 0..511

    int st = steps_p[0];
    if (st <= 0 || st > 1000000000) {
        float f = __int_as_float(st);
        st = (f > 0.5f && f < 1e9f) ? (int)(f + 0.5f) : 1;
    }
    float bias_corr = (float)(1.0 - pow(0.99, (double)st));

    float cs_new_t = 0.99f * cluster_size[t] + 0.01f * g_counts[t];
    float cs_bc_t  = cs_new_t / bias_corr;
    sred[t] = cs_bc_t;
    if (blockIdx.x == 0) outp[OFF_CS + t] = cs_new_t;
    __syncthreads();
    #pragma unroll
    for (int d = 256; d >= 1; d >>= 1) {
        if (t < d) sred[t] += sred[t + d];
        __syncthreads();
    }
    float nsum = sred[0];

    // this block's 8 codes x 64 channels
    int sc = blockIdx.x * 8 + (t >> 6);
    int c  = t & 63;
    float cs_bc_s = (0.99f * cluster_size[sc] + 0.01f * g_counts[sc]) / bias_corr;
    float upd = (cs_bc_s + 1e-7f) / (nsum + (float)S * 1e-7f) * nsum;
    int i = sc * C + c;
    float ew = 0.99f * ema_w[i] + 0.01f * g_dw[i];
    outp[OFF_EW + i]  = ew;
    outp[OFF_NCB + i] = (ew / bias_corr) / upd;

    if (blockIdx.x == 0 && t == 0) outp[OFF_LOSS] = g_loss / 8388608.0f;
}

__global__ void vq_dummy_kernel() {}

// ---------------- launch (main at absolute launch slot #4 for ncu) ----------------
extern "C" void kernel_launch(void* const* d_in, const int* in_sizes, int n_in,
                              void* d_out, int out_size) {
    const float* x            = (const float*)d_in[0];
    const float* codebook     = (const float*)d_in[1];
    const float* ema_w        = (const float*)d_in[2];
    const float* cluster_size = (const float*)d_in[3];
    const int*   steps        = (const int*)d_in[4];
    float* outp = (float*)d_out;

    cudaFuncSetAttribute(vq_main_kernel,
                         cudaFuncAttributeMaxDynamicSharedMemorySize, SMEM_BYTES);

    vq_prep_kernel<<<64, 256>>>(codebook);
    vq_dummy_kernel<<<1, 32>>>();
    vq_dummy_kernel<<<1, 32>>>();
    vq_main_kernel<<<NTOK / TOK, TPB, SMEM_BYTES>>>(x, codebook, outp);
    vq_finalize_kernel<<<64, 512>>>(ema_w, cluster_size, steps, outp);
}

// round 14
// speedup vs baseline: 1.7238x; 1.7238x over previous
#include <cuda_runtime.h>
#include <cuda_bf16.h>
#include <cstdint>
#include <math.h>

#define C     64
#define S     512
#define P     4096
#define NB    32
#define NTOK  (NB * P)          // 131072
#define TOK   128               // tokens per block
#define TPB   256
#define CAND  16

// output layout (float32, tuple flattened in order)
#define OFF_LOSS 0
#define OFF_IDX  1
#define OFF_OUT  (OFF_IDX + NTOK)
#define OFF_NCB  (OFF_OUT + NTOK * C)
#define OFF_CS   (OFF_NCB + S * C)
#define OFF_EW   (OFF_CS + S)

// smem byte layout
#define SMB_TOK   0              // fp32 tok[C][TOK]        32768
#define SMB_A     32768          // bf16 A[128][64]         16384 } union: fp32 xq[C][TOK]
#define SMB_B     49152          // bf16 B[256][64] x2 subtiles 32768 }
#define SMB_SCN   81920          // fp32 [S]                 2048
#define SMB_STN   83968          // fp32 [TOK]                512
#define SMB_GMIN  84480          // u32  [TOK] ordered keys   512
#define SMB_THR   84992          // fp32 [TOK]                512
#define SMB_SBI   85504          // int  [TOK]                512
#define SMB_CND   86016          // int  [TOK][CAND]         8192
#define SMB_CNT   94208          // int  [TOK]                512
#define SMB_PBV   94720          // fp32 [TPB]               1024
#define SMB_PBI   95744          // int  [TPB]               1024
#define SMB_RED   96768          // fp32 [8]                   32
#define SMB_SMAX  96800          // u32                         4
#define SMEM_BYTES 96832

#define SW128(b) ((b) ^ (((b) >> 3) & 0x70))

// ---------------- device scratch ----------------
__device__ float g_counts[S];
__device__ float g_dw[S * C];
__device__ float g_cnorm[S];
__device__ float g_loss;
__device__ uint4 g_cbBf[S * C * 2 / 16];   // bf16 codebook [s][c], 128B rows

// ---------------- helpers ----------------
__device__ __forceinline__ unsigned smem_u32(const void* p) {
    unsigned a;
    asm("{ .reg .u64 t; cvta.to.shared.u64 t, %1; cvt.u32.u64 %0, t; }" : "=r"(a) : "l"(p));
    return a;
}
__device__ __forceinline__ void ldmx4(unsigned& r0, unsigned& r1, unsigned& r2, unsigned& r3,
                                      unsigned addr) {
    asm volatile("ldmatrix.sync.aligned.m8n8.x4.shared.b16 {%0,%1,%2,%3}, [%4];"
                 : "=r"(r0), "=r"(r1), "=r"(r2), "=r"(r3) : "r"(addr));
}
__device__ __forceinline__ void ldmx2(unsigned& r0, unsigned& r1, unsigned addr) {
    asm volatile("ldmatrix.sync.aligned.m8n8.x2.shared.b16 {%0,%1}, [%2];"
                 : "=r"(r0), "=r"(r1) : "r"(addr));
}
__device__ __forceinline__ void mma_bf16(float* d, const unsigned* a, const unsigned* b) {
    asm volatile("mma.sync.aligned.m16n8k16.row.col.f32.bf16.bf16.f32 "
                 "{%0,%1,%2,%3}, {%4,%5,%6,%7}, {%8,%9}, {%0,%1,%2,%3};"
                 : "+f"(d[0]), "+f"(d[1]), "+f"(d[2]), "+f"(d[3])
                 : "r"(a[0]), "r"(a[1]), "r"(a[2]), "r"(a[3]), "r"(b[0]), "r"(b[1]));
}
// ordered-int encode/decode for float atomicMin over any-sign floats
__device__ __forceinline__ unsigned fkey(float f) {
    unsigned b = __float_as_uint(f);
    return b ^ ((b & 0x80000000u) ? 0xffffffffu : 0x80000000u);
}
__device__ __forceinline__ float fdec(unsigned k) {
    unsigned b = (k & 0x80000000u) ? (k ^ 0x80000000u) : ~k;
    return __uint_as_float(b);
}

// exact reference-lattice distance for (token t, code s)
__device__ __forceinline__ float rescore_one(const float* tokp, int t, int s, float A,
                                             const float* scn, const float* codebook) {
    const float4* cr = (const float4*)(codebook + s * C);
    float B = 0.f;
    #pragma unroll
    for (int q = 0; q < 16; q++) {
        float4 w = __ldg(cr + q);
        int c = q * 4;
        B = fmaf(tokp[(c + 0) * TOK + t], w.x, B);
        B = fmaf(tokp[(c + 1) * TOK + t], w.y, B);
        B = fmaf(tokp[(c + 2) * TOK + t], w.z, B);
        B = fmaf(tokp[(c + 3) * TOK + t], w.w, B);
    }
    return __fadd_rn(__fmaf_rn(-2.0f, B, A), scn[s]);
}

// ---------------- prep ----------------
__global__ void vq_prep_kernel(const float* __restrict__ codebook) {
    int gid = blockIdx.x * blockDim.x + threadIdx.x;
    if (gid < S * C / 4) {
        float4 v = ((const float4*)codebook)[gid];
        __nv_bfloat162 q0 = __floats2bfloat162_rn(v.x, v.y);
        __nv_bfloat162 q1 = __floats2bfloat162_rn(v.z, v.w);
        uint2 w;
        w.x = *(unsigned*)&q0; w.y = *(unsigned*)&q1;
        ((uint2*)g_cbBf)[gid] = w;
        ((float4*)g_dw)[gid] = make_float4(0.f, 0.f, 0.f, 0.f);
    }
    int r = gid - S * C / 4;
    if (r >= 0 && r < S) {
        const float* row = codebook + r * C;
        float acc = 0.f;
        #pragma unroll
        for (int c = 0; c < C; c++)
            acc = __fadd_rn(acc, __fmul_rn(row[c], row[c]));
        g_cnorm[r] = acc;
        g_counts[r] = 0.f;
        if (r == 0) g_loss = 0.f;
    }
}

// ---------------- main ----------------
__global__ void __launch_bounds__(TPB, 2)
vq_main_kernel(const float* __restrict__ x,
               const float* __restrict__ codebook,
               float* __restrict__ outp) {
    extern __shared__ char smc[];
    float* tok  = (float*)(smc + SMB_TOK);
    float* scr  = (float*)(smc + SMB_A);     // fp32 view of A/B union (xq tile)
    float* scn  = (float*)(smc + SMB_SCN);
    float* stn2 = (float*)(smc + SMB_STN);
    unsigned* sgmin = (unsigned*)(smc + SMB_GMIN);
    float* sthr = (float*)(smc + SMB_THR);
    int*   sbi  = (int*)(smc + SMB_SBI);
    int*   scand= (int*)(smc + SMB_CND);
    int*   scnt = (int*)(smc + SMB_CNT);
    float* pbv  = (float*)(smc + SMB_PBV);
    int*   pbi  = (int*)(smc + SMB_PBI);
    float* sred = (float*)(smc + SMB_RED);
    unsigned* smaxb = (unsigned*)(smc + SMB_SMAX);

    const unsigned sbase = smem_u32(smc);
    const int tid  = threadIdx.x;
    const int w    = tid >> 5;
    const int lane = tid & 31;
    const int tw   = w & 3;        // token tile (32 tokens)
    const int sw   = w >> 2;       // code half within each round
    const int b    = blockIdx.x;
    const int n    = b >> 5;
    const int p0   = (b & 31) * TOK;
    const float* xb = x + (size_t)n * C * P + p0;

    if (tid == 0) *smaxb = 0;
    if (tid < TOK) { scnt[tid] = 0; sgmin[tid] = 0xffffffffu; }
    __syncthreads();

    // code norms + block max
    {
        float mx = 0.f;
        for (int i = tid; i < S; i += TPB) {
            float v = g_cnorm[i];
            scn[i] = v;
            mx = fmaxf(mx, v);
        }
        atomicMax((int*)smaxb, __float_as_int(mx));
    }

    // x tile fp32 [c][t]
    for (int v = tid; v < C * TOK / 4; v += TPB) {
        int c = v >> 5, q = v & 31;
        *(float4*)(tok + c * TOK + q * 4) = *(const float4*)(xb + c * P + q * 4);
    }
    __syncthreads();

    // token norms (reference rounding)
    if (tid < TOK) {
        float a = 0.f;
        #pragma unroll
        for (int c = 0; c < C; c++) {
            float v = tok[c * TOK + tid];
            a = __fadd_rn(a, __fmul_rn(v, v));
        }
        stn2[tid] = a;
    }

    // convert A tile to bf16 [t][k], 128B SW128 rows
    {
        int t = tid >> 1, half = tid & 1, k0 = half * 32;
        #pragma unroll
        for (int q = 0; q < 4; q++) {
            unsigned u[4];
            #pragma unroll
            for (int j = 0; j < 4; j++) {
                int k = k0 + q * 8 + j * 2;
                __nv_bfloat162 pr = __floats2bfloat162_rn(tok[k * TOK + t], tok[(k + 1) * TOK + t]);
                u[j] = *(unsigned*)&pr;
            }
            unsigned byte = (unsigned)(t * 128 + half * 64 + q * 16);
            *(uint4*)(smc + SMB_A + SW128(byte)) = make_uint4(u[0], u[1], u[2], u[3]);
        }
    }
    __syncthreads();

    // A fragments: 2 m-tiles (32 tokens) x 64 k per warp
    unsigned afr[2][4][4];
    #pragma unroll
    for (int mi = 0; mi < 2; mi++)
        #pragma unroll
        for (int kc = 0; kc < 4; kc++) {
            unsigned byte = (unsigned)((tw * 32 + mi * 16 + (lane & 15)) * 128 + kc * 32 + (lane >> 4) * 16);
            ldmx4(afr[mi][kc][0], afr[mi][kc][1], afr[mi][kc][2], afr[mi][kc][3],
                  sbase + SMB_A + SW128(byte));
        }

    // hoisted B-fragment addresses (SW128 xor is jt-invariant; step +1024B/jt)
    unsigned baddr[4];
    #pragma unroll
    for (int kc = 0; kc < 4; kc++) {
        unsigned byte = (unsigned)(sw * 16384 + (lane & 7) * 128 + kc * 32 + ((lane >> 3) & 1) * 16);
        baddr[kc] = sbase + SMB_B + SW128(byte);
    }

    const int g  = lane >> 2;      // fragment row group
    const int qq = lane & 3;       // fragment col pair
    const int t0 = tw * 32 + g;    // token rows: t0, t0+8, t0+16, t0+24
    const float smax = __int_as_float(*(int*)smaxb);

    // ---- scan 1: screened global min per token ----
    {
        float rmin[4] = {3.4e38f, 3.4e38f, 3.4e38f, 3.4e38f};
        for (int r = 0; r < 2; r++) {
            // stage 256 codes (two 16KB subtiles)
            for (int task = tid; task < 512; task += TPB) {
                int row = task >> 1, half = task & 1;
                const uint4* src = g_cbBf + (r * 256 + row) * 8 + half * 4;
                #pragma unroll
                for (int q = 0; q < 4; q++) {
                    unsigned byte = (unsigned)(row * 128 + half * 64 + q * 16);
                    *(uint4*)(smc + SMB_B + SW128(byte)) = src[q];
                }
            }
            __syncthreads();
            #pragma unroll 2
            for (int jt = 0; jt < 16; jt++) {
                unsigned bfr[4][2];
                #pragma unroll
                for (int kc = 0; kc < 4; kc++)
                    ldmx2(bfr[kc][0], bfr[kc][1], baddr[kc] + (unsigned)jt * 1024);
                // split accumulators: 4 independent chains of depth 2
                float d0A[4] = {0,0,0,0}, d0B[4] = {0,0,0,0};
                float d1A[4] = {0,0,0,0}, d1B[4] = {0,0,0,0};
                mma_bf16(d0A, afr[0][0], bfr[0]);
                mma_bf16(d1A, afr[1][0], bfr[0]);
                mma_bf16(d0B, afr[0][1], bfr[1]);
                mma_bf16(d1B, afr[1][1], bfr[1]);
                mma_bf16(d0A, afr[0][2], bfr[2]);
                mma_bf16(d1A, afr[1][2], bfr[2]);
                mma_bf16(d0B, afr[0][3], bfr[3]);
                mma_bf16(d1B, afr[1][3], bfr[3]);

                int s0 = r * 256 + sw * 128 + jt * 8 + qq * 2;
                float cn0 = scn[s0], cn1 = scn[s0 + 1];
                rmin[0] = fminf(rmin[0], fminf(__fmaf_rn(-2.f, d0A[0] + d0B[0], cn0),
                                               __fmaf_rn(-2.f, d0A[1] + d0B[1], cn1)));
                rmin[1] = fminf(rmin[1], fminf(__fmaf_rn(-2.f, d0A[2] + d0B[2], cn0),
                                               __fmaf_rn(-2.f, d0A[3] + d0B[3], cn1)));
                rmin[2] = fminf(rmin[2], fminf(__fmaf_rn(-2.f, d1A[0] + d1B[0], cn0),
                                               __fmaf_rn(-2.f, d1A[1] + d1B[1], cn1)));
                rmin[3] = fminf(rmin[3], fminf(__fmaf_rn(-2.f, d1A[2] + d1B[2], cn0),
                                               __fmaf_rn(-2.f, d1A[3] + d1B[3], cn1)));
            }
            __syncthreads();
        }
        #pragma unroll
        for (int i = 0; i < 4; i++) {
            rmin[i] = fminf(rmin[i], __shfl_xor_sync(0xffffffffu, rmin[i], 1));
            rmin[i] = fminf(rmin[i], __shfl_xor_sync(0xffffffffu, rmin[i], 2));
        }
        if (qq == 0) {
            atomicMin(&sgmin[t0],      fkey(rmin[0]));
            atomicMin(&sgmin[t0 + 8],  fkey(rmin[1]));
            atomicMin(&sgmin[t0 + 16], fkey(rmin[2]));
            atomicMin(&sgmin[t0 + 24], fkey(rmin[3]));
        }
    }
    __syncthreads();

    // capture thresholds: final gmin + margin (2x bf16 dot error bound + 25%)
    if (tid < TOK)
        sthr[tid] = fdec(sgmin[tid]) + 1.25f * 0.03125f * sqrtf(stn2[tid] * smax) + 1e-5f;
    __syncthreads();

    // ---- scan 2: capture candidates vs final threshold ----
    // process r=1 FIRST: codes 256..511 are still resident in the B tile from
    // scan 1's last round (no writes to B since), so one staging is skipped.
    {
        const float thr0 = sthr[t0], thr1 = sthr[t0 + 8], thr2 = sthr[t0 + 16], thr3 = sthr[t0 + 24];
        #pragma unroll
        for (int rr = 0; rr < 2; rr++) {
            const int r = 1 - rr;              // r=1 (resident) then r=0
            if (rr == 1) {
                for (int task = tid; task < 512; task += TPB) {
                    int row = task >> 1, half = task & 1;
                    const uint4* src = g_cbBf + (r * 256 + row) * 8 + half * 4;
                    #pragma unroll
                    for (int q = 0; q < 4; q++) {
                        unsigned byte = (unsigned)(row * 128 + half * 64 + q * 16);
                        *(uint4*)(smc + SMB_B + SW128(byte)) = src[q];
                    }
                }
                __syncthreads();
            }
            #pragma unroll 2
            for (int jt = 0; jt < 16; jt++) {
                unsigned bfr[4][2];
                #pragma unroll
                for (int kc = 0; kc < 4; kc++)
                    ldmx2(bfr[kc][0], bfr[kc][1], baddr[kc] + (unsigned)jt * 1024);
                float d0A[4] = {0,0,0,0}, d0B[4] = {0,0,0,0};
                float d1A[4] = {0,0,0,0}, d1B[4] = {0,0,0,0};
                mma_bf16(d0A, afr[0][0], bfr[0]);
                mma_bf16(d1A, afr[1][0], bfr[0]);
                mma_bf16(d0B, afr[0][1], bfr[1]);
                mma_bf16(d1B, afr[1][1], bfr[1]);
                mma_bf16(d0A, afr[0][2], bfr[2]);
                mma_bf16(d1A, afr[1][2], bfr[2]);
                mma_bf16(d0B, afr[0][3], bfr[3]);
                mma_bf16(d1B, afr[1][3], bfr[3]);

                int s0 = r * 256 + sw * 128 + jt * 8 + qq * 2;
                float cn0 = scn[s0], cn1 = scn[s0 + 1];
                float v;
                v = __fmaf_rn(-2.f, d0A[0] + d0B[0], cn0);
                if (v <= thr0) { int sl = atomicAdd(&scnt[t0], 1); if (sl < CAND) scand[t0 * CAND + sl] = s0; }
                v = __fmaf_rn(-2.f, d0A[1] + d0B[1], cn1);
                if (v <= thr0) { int sl = atomicAdd(&scnt[t0], 1); if (sl < CAND) scand[t0 * CAND + sl] = s0 + 1; }
                v = __fmaf_rn(-2.f, d0A[2] + d0B[2], cn0);
                if (v <= thr1) { int sl = atomicAdd(&scnt[t0 + 8], 1); if (sl < CAND) scand[(t0 + 8) * CAND + sl] = s0; }
                v = __fmaf_rn(-2.f, d0A[3] + d0B[3], cn1);
                if (v <= thr1) { int sl = atomicAdd(&scnt[t0 + 8], 1); if (sl < CAND) scand[(t0 + 8) * CAND + sl] = s0 + 1; }
                v = __fmaf_rn(-2.f, d1A[0] + d1B[0], cn0);
                if (v <= thr2) { int sl = atomicAdd(&scnt[t0 + 16], 1); if (sl < CAND) scand[(t0 + 16) * CAND + sl] = s0; }
                v = __fmaf_rn(-2.f, d1A[1] + d1B[1], cn1);
                if (v <= thr2) { int sl = atomicAdd(&scnt[t0 + 16], 1); if (sl < CAND) scand[(t0 + 16) * CAND + sl] = s0 + 1; }
                v = __fmaf_rn(-2.f, d1A[2] + d1B[2], cn0);
                if (v <= thr3) { int sl = atomicAdd(&scnt[t0 + 24], 1); if (sl < CAND) scand[(t0 + 24) * CAND + sl] = s0; }
                v = __fmaf_rn(-2.f, d1A[3] + d1B[3], cn1);
                if (v <= thr3) { int sl = atomicAdd(&scnt[t0 + 24], 1); if (sl < CAND) scand[(t0 + 24) * CAND + sl] = s0 + 1; }
            }
            __syncthreads();
        }
    }

    // ---- exact rescore (2 threads per token) ----
    {
        int t = tid & 127;
        int half = tid >> 7;
        float A = stn2[t];
        float bestd = 3.4e38f;
        int bests = 1 << 30;
        int cnt = scnt[t];
        if (cnt <= CAND) {
            for (int i = half; i < cnt; i += 2) {
                int s = scand[t * CAND + i];
                float d = rescore_one(tok, t, s, A, scn, codebook);
                if (d < bestd || (d == bestd && s < bests)) { bestd = d; bests = s; }
            }
        } else {
            for (int s = half; s < S; s += 2) {
                float d = rescore_one(tok, t, s, A, scn, codebook);
                if (d < bestd || (d == bestd && s < bests)) { bestd = d; bests = s; }
            }
        }
        pbv[tid] = bestd;
        pbi[tid] = bests;
    }
    __syncthreads();
    if (tid < TOK) {
        float d1 = pbv[tid];       int s1 = pbi[tid];
        float d2 = pbv[tid + 128]; int s2 = pbi[tid + 128];
        int bs = (d2 < d1 || (d2 == d1 && s2 < s1)) ? s2 : s1;
        sbi[tid] = bs;
        outp[OFF_IDX + (size_t)n * P + p0 + tid] = (float)bs;
        atomicAdd(&g_counts[bs], 1.0f);
    }
    __syncthreads();

    // gather xq into scr[c][t] (overwrites A/B tiles) + dw scatter
    {
        int t = tid >> 1, c0 = (tid & 1) * 32;
        int sdx = sbi[t];
        const float4* crow = (const float4*)(codebook + sdx * C + c0);
        #pragma unroll
        for (int q = 0; q < 8; q++) {
            float4 v = crow[q];
            int c = c0 + q * 4;
            scr[(c + 0) * TOK + t] = v.x;
            scr[(c + 1) * TOK + t] = v.y;
            scr[(c + 2) * TOK + t] = v.z;
            scr[(c + 3) * TOK + t] = v.w;
        }
        float* dwrow = g_dw + sdx * C + c0;
        #pragma unroll 8
        for (int j = 0; j < 32; j++)
            atomicAdd(&dwrow[j], tok[(c0 + j) * TOK + t]);
    }
    __syncthreads();

    // straight-through out + commitment loss
    float lsum = 0.f;
    float* ob = outp + OFF_OUT + (size_t)n * C * P + p0;
    for (int v = tid; v < C * TOK; v += TPB) {
        int c = v >> 7, t = v & 127;
        float xv = tok[c * TOK + t];
        float qv = scr[c * TOK + t];
        ob[c * P + t] = xv + (qv - xv);
        float dd = xv - qv;
        lsum = fmaf(dd, dd, lsum);
    }
    #pragma unroll
    for (int d = 16; d >= 1; d >>= 1) lsum += __shfl_xor_sync(0xffffffffu, lsum, d);
    if (lane == 0) sred[w] = lsum;
    __syncthreads();
    if (tid == 0) {
        float tot = 0.f;
        #pragma unroll
        for (int q = 0; q < TPB / 32; q++) tot += sred[q];
        atomicAdd(&g_loss, tot);
    }
}

// ---------------- finalize: 64 blocks, each redundantly reduces nsum ----------------
__global__ void vq_finalize_kernel(const float* __restrict__ ema_w,
                                   const float* __restrict__ cluster_size,
                                   const int* __restrict__ steps_p,
                                   float* __restrict__ outp) {
    __shared__ float sred[S];
    int t = threadIdx.x;          // 0..511

    int st = steps_p[0];
    if (st <= 0 || st > 1000000000) {
        float f = __int_as_float(st);
        st = (f > 0.5f && f < 1e9f) ? (int)(f + 0.5f) : 1;
    }
    float bias_corr = (float)(1.0 - pow(0.99, (double)st));

    float cs_new_t = 0.99f * cluster_size[t] + 0.01f * g_counts[t];
    float cs_bc_t  = cs_new_t / bias_corr;
    sred[t] = cs_bc_t;
    if (blockIdx.x == 0) outp[OFF_CS + t] = cs_new_t;
    __syncthreads();
    #pragma unroll
    for (int d = 256; d >= 1; d >>= 1) {
        if (t < d) sred[t] += sred[t + d];
        __syncthreads();
    }
    float nsum = sred[0];

    // this block's 8 codes x 64 channels
    int sc = blockIdx.x * 8 + (t >> 6);
    int c  = t & 63;
    float cs_bc_s = (0.99f * cluster_size[sc] + 0.01f * g_counts[sc]) / bias_corr;
    float upd = (cs_bc_s + 1e-7f) / (nsum + (float)S * 1e-7f) * nsum;
    int i = sc * C + c;
    float ew = 0.99f * ema_w[i] + 0.01f * g_dw[i];
    outp[OFF_EW + i]  = ew;
    outp[OFF_NCB + i] = (ew / bias_corr) / upd;

    if (blockIdx.x == 0 && t == 0) outp[OFF_LOSS] = g_loss / 8388608.0f;
}

// ---------------- launch ----------------
extern "C" void kernel_launch(void* const* d_in, const int* in_sizes, int n_in,
                              void* d_out, int out_size) {
    const float* x            = (const float*)d_in[0];
    const float* codebook     = (const float*)d_in[1];
    const float* ema_w        = (const float*)d_in[2];
    const float* cluster_size = (const float*)d_in[3];
    const int*   steps        = (const int*)d_in[4];
    float* outp = (float*)d_out;

    cudaFuncSetAttribute(vq_main_kernel,
                         cudaFuncAttributeMaxDynamicSharedMemorySize, SMEM_BYTES);

    vq_prep_kernel<<<64, 256>>>(codebook);
    vq_main_kernel<<<NTOK / TOK, TPB, SMEM_BYTES>>>(x, codebook, outp);
    vq_finalize_kernel<<<64, 512>>>(ema_w, cluster_size, steps, outp);
}

// round 15
// speedup vs baseline: 1.7847x; 1.0353x over previous
#include <cuda_runtime.h>
#include <cuda_bf16.h>
#include <cstdint>
#include <math.h>

#define C     64
#define S     512
#define P     4096
#define NB    32
#define NTOK  (NB * P)          // 131072
#define TOK   128               // tokens per block
#define TPB   256
#define CAND  16

// output layout (float32, tuple flattened in order)
#define OFF_LOSS 0
#define OFF_IDX  1
#define OFF_OUT  (OFF_IDX + NTOK)
#define OFF_NCB  (OFF_OUT + NTOK * C)
#define OFF_CS   (OFF_NCB + S * C)
#define OFF_EW   (OFF_CS + S)

// smem byte layout
#define SMB_TOK   0              // fp32 tok[C][TOK]        32768
#define SMB_A     32768          // bf16 A[128][64]         16384 } union: fp32 xq[C][TOK]
#define SMB_B     49152          // bf16 B[256][64] x2 subtiles 32768 }
#define SMB_SCN   81920          // fp32 [S]                 2048
#define SMB_STN   83968          // fp32 [TOK]                512
#define SMB_GMIN  84480          // u32  [TOK] ordered keys   512
#define SMB_THR   84992          // fp32 [TOK]                512
#define SMB_SBI   85504          // int  [TOK]                512
#define SMB_CND   86016          // int  [TOK][CAND]         8192
#define SMB_CNT   94208          // int  [TOK]                512
#define SMB_PBV   94720          // fp32 [TPB]               1024
#define SMB_PBI   95744          // int  [TPB]               1024
#define SMB_RED   96768          // fp32 [8]                   32
#define SMB_SMAX  96800          // u32                         4
#define SMEM_BYTES 96832

#define SW128(b) ((b) ^ (((b) >> 3) & 0x70))

// ---------------- device scratch ----------------
__device__ float g_counts[S];
__device__ float g_dw[S * C];
__device__ float g_cnorm[S];
__device__ float g_loss;
__device__ uint4 g_cbBf[S * C * 2 / 16];   // bf16 codebook [s][c], 128B rows

// ---------------- helpers ----------------
__device__ __forceinline__ unsigned smem_u32(const void* p) {
    unsigned a;
    asm("{ .reg .u64 t; cvta.to.shared.u64 t, %1; cvt.u32.u64 %0, t; }" : "=r"(a) : "l"(p));
    return a;
}
__device__ __forceinline__ void ldmx4(unsigned& r0, unsigned& r1, unsigned& r2, unsigned& r3,
                                      unsigned addr) {
    asm volatile("ldmatrix.sync.aligned.m8n8.x4.shared.b16 {%0,%1,%2,%3}, [%4];"
                 : "=r"(r0), "=r"(r1), "=r"(r2), "=r"(r3) : "r"(addr));
}
__device__ __forceinline__ void ldmx2(unsigned& r0, unsigned& r1, unsigned addr) {
    asm volatile("ldmatrix.sync.aligned.m8n8.x2.shared.b16 {%0,%1}, [%2];"
                 : "=r"(r0), "=r"(r1) : "r"(addr));
}
__device__ __forceinline__ void mma_bf16(float* d, const unsigned* a, const unsigned* b) {
    asm volatile("mma.sync.aligned.m16n8k16.row.col.f32.bf16.bf16.f32 "
                 "{%0,%1,%2,%3}, {%4,%5,%6,%7}, {%8,%9}, {%0,%1,%2,%3};"
                 : "+f"(d[0]), "+f"(d[1]), "+f"(d[2]), "+f"(d[3])
                 : "r"(a[0]), "r"(a[1]), "r"(a[2]), "r"(a[3]), "r"(b[0]), "r"(b[1]));
}
// ordered-int encode/decode for float atomicMin over any-sign floats
__device__ __forceinline__ unsigned fkey(float f) {
    unsigned b = __float_as_uint(f);
    return b ^ ((b & 0x80000000u) ? 0xffffffffu : 0x80000000u);
}
__device__ __forceinline__ float fdec(unsigned k) {
    unsigned b = (k & 0x80000000u) ? (k ^ 0x80000000u) : ~k;
    return __uint_as_float(b);
}

// exact reference-lattice distance for (token t, code s)
__device__ __forceinline__ float rescore_one(const float* tokp, int t, int s, float A,
                                             const float* scn, const float* codebook) {
    const float4* cr = (const float4*)(codebook + s * C);
    float B = 0.f;
    #pragma unroll
    for (int q = 0; q < 16; q++) {
        float4 w = __ldg(cr + q);
        int c = q * 4;
        B = fmaf(tokp[(c + 0) * TOK + t], w.x, B);
        B = fmaf(tokp[(c + 1) * TOK + t], w.y, B);
        B = fmaf(tokp[(c + 2) * TOK + t], w.z, B);
        B = fmaf(tokp[(c + 3) * TOK + t], w.w, B);
    }
    return __fadd_rn(__fmaf_rn(-2.0f, B, A), scn[s]);
}

// ---------------- prep ----------------
// cnorm threads first (gid < S): latency-critical serial chain starts with
// all 16 row loads already in flight (MLP=16). Rounding order unchanged.
__global__ void vq_prep_kernel(const float* __restrict__ codebook) {
    int gid = blockIdx.x * blockDim.x + threadIdx.x;

    if (gid < S) {
        const float4* row = (const float4*)(codebook + gid * C);
        float4 rv[16];
        #pragma unroll
        for (int q = 0; q < 16; q++) rv[q] = __ldg(row + q);
        float acc = 0.f;
        #pragma unroll
        for (int q = 0; q < 16; q++) {
            acc = __fadd_rn(acc, __fmul_rn(rv[q].x, rv[q].x));
            acc = __fadd_rn(acc, __fmul_rn(rv[q].y, rv[q].y));
            acc = __fadd_rn(acc, __fmul_rn(rv[q].z, rv[q].z));
            acc = __fadd_rn(acc, __fmul_rn(rv[q].w, rv[q].w));
        }
        g_cnorm[gid] = acc;
        g_counts[gid] = 0.f;
        if (gid == 0) g_loss = 0.f;
    }

    int v = gid - S;
    if (v >= 0 && v < S * C / 4) {
        float4 c4 = ((const float4*)codebook)[v];
        __nv_bfloat162 q0 = __floats2bfloat162_rn(c4.x, c4.y);
        __nv_bfloat162 q1 = __floats2bfloat162_rn(c4.z, c4.w);
        uint2 wv;
        wv.x = *(unsigned*)&q0; wv.y = *(unsigned*)&q1;
        ((uint2*)g_cbBf)[v] = wv;
        ((float4*)g_dw)[v] = make_float4(0.f, 0.f, 0.f, 0.f);
    }
}

// ---------------- main ----------------
__global__ void __launch_bounds__(TPB, 2)
vq_main_kernel(const float* __restrict__ x,
               const float* __restrict__ codebook,
               float* __restrict__ outp) {
    extern __shared__ char smc[];
    float* tok  = (float*)(smc + SMB_TOK);
    float* scr  = (float*)(smc + SMB_A);     // fp32 view of A/B union (xq tile)
    float* scn  = (float*)(smc + SMB_SCN);
    float* stn2 = (float*)(smc + SMB_STN);
    unsigned* sgmin = (unsigned*)(smc + SMB_GMIN);
    float* sthr = (float*)(smc + SMB_THR);
    int*   sbi  = (int*)(smc + SMB_SBI);
    int*   scand= (int*)(smc + SMB_CND);
    int*   scnt = (int*)(smc + SMB_CNT);
    float* pbv  = (float*)(smc + SMB_PBV);
    int*   pbi  = (int*)(smc + SMB_PBI);
    float* sred = (float*)(smc + SMB_RED);
    unsigned* smaxb = (unsigned*)(smc + SMB_SMAX);

    const unsigned sbase = smem_u32(smc);
    const int tid  = threadIdx.x;
    const int w    = tid >> 5;
    const int lane = tid & 31;
    const int tw   = w & 3;        // token tile (32 tokens)
    const int sw   = w >> 2;       // code half within each round
    const int b    = blockIdx.x;
    const int n    = b >> 5;
    const int p0   = (b & 31) * TOK;
    const float* xb = x + (size_t)n * C * P + p0;

    if (tid == 0) *smaxb = 0;
    if (tid < TOK) { scnt[tid] = 0; sgmin[tid] = 0xffffffffu; }
    __syncthreads();

    // code norms + block max
    {
        float mx = 0.f;
        for (int i = tid; i < S; i += TPB) {
            float v = g_cnorm[i];
            scn[i] = v;
            mx = fmaxf(mx, v);
        }
        atomicMax((int*)smaxb, __float_as_int(mx));
    }

    // x tile fp32 [c][t]
    for (int v = tid; v < C * TOK / 4; v += TPB) {
        int c = v >> 5, q = v & 31;
        *(float4*)(tok + c * TOK + q * 4) = *(const float4*)(xb + c * P + q * 4);
    }
    __syncthreads();

    // token norms (reference rounding)
    if (tid < TOK) {
        float a = 0.f;
        #pragma unroll
        for (int c = 0; c < C; c++) {
            float v = tok[c * TOK + tid];
            a = __fadd_rn(a, __fmul_rn(v, v));
        }
        stn2[tid] = a;
    }

    // convert A tile to bf16 [t][k], 128B SW128 rows
    {
        int t = tid >> 1, half = tid & 1, k0 = half * 32;
        #pragma unroll
        for (int q = 0; q < 4; q++) {
            unsigned u[4];
            #pragma unroll
            for (int j = 0; j < 4; j++) {
                int k = k0 + q * 8 + j * 2;
                __nv_bfloat162 pr = __floats2bfloat162_rn(tok[k * TOK + t], tok[(k + 1) * TOK + t]);
                u[j] = *(unsigned*)&pr;
            }
            unsigned byte = (unsigned)(t * 128 + half * 64 + q * 16);
            *(uint4*)(smc + SMB_A + SW128(byte)) = make_uint4(u[0], u[1], u[2], u[3]);
        }
    }
    __syncthreads();

    // A fragments: 2 m-tiles (32 tokens) x 64 k per warp
    unsigned afr[2][4][4];
    #pragma unroll
    for (int mi = 0; mi < 2; mi++)
        #pragma unroll
        for (int kc = 0; kc < 4; kc++) {
            unsigned byte = (unsigned)((tw * 32 + mi * 16 + (lane & 15)) * 128 + kc * 32 + (lane >> 4) * 16);
            ldmx4(afr[mi][kc][0], afr[mi][kc][1], afr[mi][kc][2], afr[mi][kc][3],
                  sbase + SMB_A + SW128(byte));
        }

    // hoisted B-fragment addresses (SW128 xor is jt-invariant; step +1024B/jt)
    unsigned baddr[4];
    #pragma unroll
    for (int kc = 0; kc < 4; kc++) {
        unsigned byte = (unsigned)(sw * 16384 + (lane & 7) * 128 + kc * 32 + ((lane >> 3) & 1) * 16);
        baddr[kc] = sbase + SMB_B + SW128(byte);
    }

    const int g  = lane >> 2;      // fragment row group
    const int qq = lane & 3;       // fragment col pair
    const int t0 = tw * 32 + g;    // token rows: t0, t0+8, t0+16, t0+24
    const float smax = __int_as_float(*(int*)smaxb);

    // ---- scan 1: screened global min per token ----
    {
        float rmin[4] = {3.4e38f, 3.4e38f, 3.4e38f, 3.4e38f};
        for (int r = 0; r < 2; r++) {
            // stage 256 codes (two 16KB subtiles)
            for (int task = tid; task < 512; task += TPB) {
                int row = task >> 1, half = task & 1;
                const uint4* src = g_cbBf + (r * 256 + row) * 8 + half * 4;
                #pragma unroll
                for (int q = 0; q < 4; q++) {
                    unsigned byte = (unsigned)(row * 128 + half * 64 + q * 16);
                    *(uint4*)(smc + SMB_B + SW128(byte)) = src[q];
                }
            }
            __syncthreads();
            #pragma unroll 2
            for (int jt = 0; jt < 16; jt++) {
                unsigned bfr[4][2];
                #pragma unroll
                for (int kc = 0; kc < 4; kc++)
                    ldmx2(bfr[kc][0], bfr[kc][1], baddr[kc] + (unsigned)jt * 1024);
                // split accumulators: 4 independent chains of depth 2
                float d0A[4] = {0,0,0,0}, d0B[4] = {0,0,0,0};
                float d1A[4] = {0,0,0,0}, d1B[4] = {0,0,0,0};
                mma_bf16(d0A, afr[0][0], bfr[0]);
                mma_bf16(d1A, afr[1][0], bfr[0]);
                mma_bf16(d0B, afr[0][1], bfr[1]);
                mma_bf16(d1B, afr[1][1], bfr[1]);
                mma_bf16(d0A, afr[0][2], bfr[2]);
                mma_bf16(d1A, afr[1][2], bfr[2]);
                mma_bf16(d0B, afr[0][3], bfr[3]);
                mma_bf16(d1B, afr[1][3], bfr[3]);

                int s0 = r * 256 + sw * 128 + jt * 8 + qq * 2;
                float cn0 = scn[s0], cn1 = scn[s0 + 1];
                rmin[0] = fminf(rmin[0], fminf(__fmaf_rn(-2.f, d0A[0] + d0B[0], cn0),
                                               __fmaf_rn(-2.f, d0A[1] + d0B[1], cn1)));
                rmin[1] = fminf(rmin[1], fminf(__fmaf_rn(-2.f, d0A[2] + d0B[2], cn0),
                                               __fmaf_rn(-2.f, d0A[3] + d0B[3], cn1)));
                rmin[2] = fminf(rmin[2], fminf(__fmaf_rn(-2.f, d1A[0] + d1B[0], cn0),
                                               __fmaf_rn(-2.f, d1A[1] + d1B[1], cn1)));
                rmin[3] = fminf(rmin[3], fminf(__fmaf_rn(-2.f, d1A[2] + d1B[2], cn0),
                                               __fmaf_rn(-2.f, d1A[3] + d1B[3], cn1)));
            }
            __syncthreads();
        }
        #pragma unroll
        for (int i = 0; i < 4; i++) {
            rmin[i] = fminf(rmin[i], __shfl_xor_sync(0xffffffffu, rmin[i], 1));
            rmin[i] = fminf(rmin[i], __shfl_xor_sync(0xffffffffu, rmin[i], 2));
        }
        if (qq == 0) {
            atomicMin(&sgmin[t0],      fkey(rmin[0]));
            atomicMin(&sgmin[t0 + 8],  fkey(rmin[1]));
            atomicMin(&sgmin[t0 + 16], fkey(rmin[2]));
            atomicMin(&sgmin[t0 + 24], fkey(rmin[3]));
        }
    }
    __syncthreads();

    // capture thresholds: final gmin + margin (2x bf16 dot error bound + 25%)
    if (tid < TOK)
        sthr[tid] = fdec(sgmin[tid]) + 1.25f * 0.03125f * sqrtf(stn2[tid] * smax) + 1e-5f;
    __syncthreads();

    // ---- scan 2: capture candidates vs final threshold ----
    // process r=1 FIRST: codes 256..511 are still resident in the B tile from
    // scan 1's last round (no writes to B since), so one staging is skipped.
    {
        const float thr0 = sthr[t0], thr1 = sthr[t0 + 8], thr2 = sthr[t0 + 16], thr3 = sthr[t0 + 24];
        #pragma unroll
        for (int rr = 0; rr < 2; rr++) {
            const int r = 1 - rr;              // r=1 (resident) then r=0
            if (rr == 1) {
                for (int task = tid; task < 512; task += TPB) {
                    int row = task >> 1, half = task & 1;
                    const uint4* src = g_cbBf + (r * 256 + row) * 8 + half * 4;
                    #pragma unroll
                    for (int q = 0; q < 4; q++) {
                        unsigned byte = (unsigned)(row * 128 + half * 64 + q * 16);
                        *(uint4*)(smc + SMB_B + SW128(byte)) = src[q];
                    }
                }
                __syncthreads();
            }
            #pragma unroll 2
            for (int jt = 0; jt < 16; jt++) {
                unsigned bfr[4][2];
                #pragma unroll
                for (int kc = 0; kc < 4; kc++)
                    ldmx2(bfr[kc][0], bfr[kc][1], baddr[kc] + (unsigned)jt * 1024);
                float d0A[4] = {0,0,0,0}, d0B[4] = {0,0,0,0};
                float d1A[4] = {0,0,0,0}, d1B[4] = {0,0,0,0};
                mma_bf16(d0A, afr[0][0], bfr[0]);
                mma_bf16(d1A, afr[1][0], bfr[0]);
                mma_bf16(d0B, afr[0][1], bfr[1]);
                mma_bf16(d1B, afr[1][1], bfr[1]);
                mma_bf16(d0A, afr[0][2], bfr[2]);
                mma_bf16(d1A, afr[1][2], bfr[2]);
                mma_bf16(d0B, afr[0][3], bfr[3]);
                mma_bf16(d1B, afr[1][3], bfr[3]);

                int s0 = r * 256 + sw * 128 + jt * 8 + qq * 2;
                float cn0 = scn[s0], cn1 = scn[s0 + 1];
                float v;
                v = __fmaf_rn(-2.f, d0A[0] + d0B[0], cn0);
                if (v <= thr0) { int sl = atomicAdd(&scnt[t0], 1); if (sl < CAND) scand[t0 * CAND + sl] = s0; }
                v = __fmaf_rn(-2.f, d0A[1] + d0B[1], cn1);
                if (v <= thr0) { int sl = atomicAdd(&scnt[t0], 1); if (sl < CAND) scand[t0 * CAND + sl] = s0 + 1; }
                v = __fmaf_rn(-2.f, d0A[2] + d0B[2], cn0);
                if (v <= thr1) { int sl = atomicAdd(&scnt[t0 + 8], 1); if (sl < CAND) scand[(t0 + 8) * CAND + sl] = s0; }
                v = __fmaf_rn(-2.f, d0A[3] + d0B[3], cn1);
                if (v <= thr1) { int sl = atomicAdd(&scnt[t0 + 8], 1); if (sl < CAND) scand[(t0 + 8) * CAND + sl] = s0 + 1; }
                v = __fmaf_rn(-2.f, d1A[0] + d1B[0], cn0);
                if (v <= thr2) { int sl = atomicAdd(&scnt[t0 + 16], 1); if (sl < CAND) scand[(t0 + 16) * CAND + sl] = s0; }
                v = __fmaf_rn(-2.f, d1A[1] + d1B[1], cn1);
                if (v <= thr2) { int sl = atomicAdd(&scnt[t0 + 16], 1); if (sl < CAND) scand[(t0 + 16) * CAND + sl] = s0 + 1; }
                v = __fmaf_rn(-2.f, d1A[2] + d1B[2], cn0);
                if (v <= thr3) { int sl = atomicAdd(&scnt[t0 + 24], 1); if (sl < CAND) scand[(t0 + 24) * CAND + sl] = s0; }
                v = __fmaf_rn(-2.f, d1A[3] + d1B[3], cn1);
                if (v <= thr3) { int sl = atomicAdd(&scnt[t0 + 24], 1); if (sl < CAND) scand[(t0 + 24) * CAND + sl] = s0 + 1; }
            }
            __syncthreads();
        }
    }

    // ---- exact rescore (2 threads per token) ----
    {
        int t = tid & 127;
        int half = tid >> 7;
        float A = stn2[t];
        float bestd = 3.4e38f;
        int bests = 1 << 30;
        int cnt = scnt[t];
        if (cnt <= CAND) {
            for (int i = half; i < cnt; i += 2) {
                int s = scand[t * CAND + i];
                float d = rescore_one(tok, t, s, A, scn, codebook);
                if (d < bestd || (d == bestd && s < bests)) { bestd = d; bests = s; }
            }
        } else {
            for (int s = half; s < S; s += 2) {
                float d = rescore_one(tok, t, s, A, scn, codebook);
                if (d < bestd || (d == bestd && s < bests)) { bestd = d; bests = s; }
            }
        }
        pbv[tid] = bestd;
        pbi[tid] = bests;
    }
    __syncthreads();
    if (tid < TOK) {
        float d1 = pbv[tid];       int s1 = pbi[tid];
        float d2 = pbv[tid + 128]; int s2 = pbi[tid + 128];
        int bs = (d2 < d1 || (d2 == d1 && s2 < s1)) ? s2 : s1;
        sbi[tid] = bs;
        outp[OFF_IDX + (size_t)n * P + p0 + tid] = (float)bs;
        atomicAdd(&g_counts[bs], 1.0f);
    }
    __syncthreads();

    // gather xq into scr[c][t] (overwrites A/B tiles) + dw scatter
    {
        int t = tid >> 1, c0 = (tid & 1) * 32;
        int sdx = sbi[t];
        const float4* crow = (const float4*)(codebook + sdx * C + c0);
        #pragma unroll
        for (int q = 0; q < 8; q++) {
            float4 v = crow[q];
            int c = c0 + q * 4;
            scr[(c + 0) * TOK + t] = v.x;
            scr[(c + 1) * TOK + t] = v.y;
            scr[(c + 2) * TOK + t] = v.z;
            scr[(c + 3) * TOK + t] = v.w;
        }
        float* dwrow = g_dw + sdx * C + c0;
        #pragma unroll 8
        for (int j = 0; j < 32; j++)
            atomicAdd(&dwrow[j], tok[(c0 + j) * TOK + t]);
    }
    __syncthreads();

    // straight-through out + commitment loss
    float lsum = 0.f;
    float* ob = outp + OFF_OUT + (size_t)n * C * P + p0;
    for (int v = tid; v < C * TOK; v += TPB) {
        int c = v >> 7, t = v & 127;
        float xv = tok[c * TOK + t];
        float qv = scr[c * TOK + t];
        ob[c * P + t] = xv + (qv - xv);
        float dd = xv - qv;
        lsum = fmaf(dd, dd, lsum);
    }
    #pragma unroll
    for (int d = 16; d >= 1; d >>= 1) lsum += __shfl_xor_sync(0xffffffffu, lsum, d);
    if (lane == 0) sred[w] = lsum;
    __syncthreads();
    if (tid == 0) {
        float tot = 0.f;
        #pragma unroll
        for (int q = 0; q < TPB / 32; q++) tot += sred[q];
        atomicAdd(&g_loss, tot);
    }
}

// ---------------- finalize: 64 blocks, each redundantly reduces nsum ----------------
__global__ void vq_finalize_kernel(const float* __restrict__ ema_w,
                                   const float* __restrict__ cluster_size,
                                   const int* __restrict__ steps_p,
                                   float* __restrict__ outp) {
    __shared__ float sred[S];
    int t = threadIdx.x;          // 0..511

    int st = steps_p[0];
    if (st <= 0 || st > 1000000000) {
        float f = __int_as_float(st);
        st = (f > 0.5f && f < 1e9f) ? (int)(f + 0.5f) : 1;
    }
    float bias_corr = (float)(1.0 - pow(0.99, (double)st));

    float cs_new_t = 0.99f * cluster_size[t] + 0.01f * g_counts[t];
    float cs_bc_t  = cs_new_t / bias_corr;
    sred[t] = cs_bc_t;
    if (blockIdx.x == 0) outp[OFF_CS + t] = cs_new_t;
    __syncthreads();
    #pragma unroll
    for (int d = 256; d >= 1; d >>= 1) {
        if (t < d) sred[t] += sred[t + d];
        __syncthreads();
    }
    float nsum = sred[0];

    // this block's 8 codes x 64 channels
    int sc = blockIdx.x * 8 + (t >> 6);
    int c  = t & 63;
    float cs_bc_s = (0.99f * cluster_size[sc] + 0.01f * g_counts[sc]) / bias_corr;
    float upd = (cs_bc_s + 1e-7f) / (nsum + (float)S * 1e-7f) * nsum;
    int i = sc * C + c;
    float ew = 0.99f * ema_w[i] + 0.01f * g_dw[i];
    outp[OFF_EW + i]  = ew;
    outp[OFF_NCB + i] = (ew / bias_corr) / upd;

    if (blockIdx.x == 0 && t == 0) outp[OFF_LOSS] = g_loss / 8388608.0f;
}

// ---------------- launch ----------------
extern "C" void kernel_launch(void* const* d_in, const int* in_sizes, int n_in,
                              void* d_out, int out_size) {
    const float* x            = (const float*)d_in[0];
    const float* codebook     = (const float*)d_in[1];
    const float* ema_w        = (const float*)d_in[2];
    const float* cluster_size = (const float*)d_in[3];
    const int*   steps        = (const int*)d_in[4];
    float* outp = (float*)d_out;

    cudaFuncSetAttribute(vq_main_kernel,
                         cudaFuncAttributeMaxDynamicSharedMemorySize, SMEM_BYTES);

    vq_prep_kernel<<<64, 256>>>(codebook);
    vq_main_kernel<<<NTOK / TOK, TPB, SMEM_BYTES>>>(x, codebook, outp);
    vq_finalize_kernel<<<64, 512>>>(ema_w, cluster_size, steps, outp);
}

// round 16
// speedup vs baseline: 1.8340x; 1.0276x over previous
#include <cuda_runtime.h>
#include <cuda_bf16.h>
#include <cstdint>
#include <math.h>

#define C     64
#define S     512
#define P     4096
#define NB    32
#define NTOK  (NB * P)          // 131072
#define TOK   128               // tokens per block
#define TPB   256
#define CAND  16

// output layout (float32, tuple flattened in order)
#define OFF_LOSS 0
#define OFF_IDX  1
#define OFF_OUT  (OFF_IDX + NTOK)
#define OFF_NCB  (OFF_OUT + NTOK * C)
#define OFF_CS   (OFF_NCB + S * C)
#define OFF_EW   (OFF_CS + S)

// smem byte layout
#define SMB_TOK   0              // fp32 tok[C][TOK]        32768
#define SMB_A     32768          // bf16 A[128][64]         16384 } union: fp32 xq[C][TOK]
#define SMB_B     49152          // bf16 B[256][64] x2 subtiles 32768 }
#define SMB_SCN   81920          // fp32 [S]                 2048
#define SMB_STN   83968          // fp32 [TOK]                512
#define SMB_GMIN  84480          // u32  [TOK] ordered keys   512
#define SMB_THR   84992          // fp32 [TOK]                512
#define SMB_SBI   85504          // int  [TOK]                512
#define SMB_CND   86016          // int  [TOK][CAND]         8192
#define SMB_CNT   94208          // int  [TOK]                512
#define SMB_PBV   94720          // fp32 [TPB]               1024
#define SMB_PBI   95744          // int  [TPB]               1024
#define SMB_RED   96768          // fp32 [8]                   32
#define SMB_SMAX  96800          // u32                         4
#define SMEM_BYTES 96832

#define SW128(b) ((b) ^ (((b) >> 3) & 0x70))

// ---------------- device scratch ----------------
__device__ float g_counts[S];
__device__ float g_dw[S * C];
__device__ float g_cnorm[S];
__device__ float g_loss;
__device__ uint4 g_cbBf[S * C * 2 / 16];   // bf16 codebook [s][c], 128B rows

// ---------------- helpers ----------------
__device__ __forceinline__ unsigned smem_u32(const void* p) {
    unsigned a;
    asm("{ .reg .u64 t; cvta.to.shared.u64 t, %1; cvt.u32.u64 %0, t; }" : "=r"(a) : "l"(p));
    return a;
}
__device__ __forceinline__ void ldmx4(unsigned& r0, unsigned& r1, unsigned& r2, unsigned& r3,
                                      unsigned addr) {
    asm volatile("ldmatrix.sync.aligned.m8n8.x4.shared.b16 {%0,%1,%2,%3}, [%4];"
                 : "=r"(r0), "=r"(r1), "=r"(r2), "=r"(r3) : "r"(addr));
}
__device__ __forceinline__ void mma_bf16(float* d, const unsigned* a, const unsigned* b) {
    asm volatile("mma.sync.aligned.m16n8k16.row.col.f32.bf16.bf16.f32 "
                 "{%0,%1,%2,%3}, {%4,%5,%6,%7}, {%8,%9}, {%0,%1,%2,%3};"
                 : "+f"(d[0]), "+f"(d[1]), "+f"(d[2]), "+f"(d[3])
                 : "r"(a[0]), "r"(a[1]), "r"(a[2]), "r"(a[3]), "r"(b[0]), "r"(b[1]));
}
// ordered-int encode/decode for float atomicMin over any-sign floats
__device__ __forceinline__ unsigned fkey(float f) {
    unsigned b = __float_as_uint(f);
    return b ^ ((b & 0x80000000u) ? 0xffffffffu : 0x80000000u);
}
__device__ __forceinline__ float fdec(unsigned k) {
    unsigned b = (k & 0x80000000u) ? (k ^ 0x80000000u) : ~k;
    return __uint_as_float(b);
}

// exact reference-lattice distance for (token t, code s)
__device__ __forceinline__ float rescore_one(const float* tokp, int t, int s, float A,
                                             const float* scn, const float* codebook) {
    const float4* cr = (const float4*)(codebook + s * C);
    float B = 0.f;
    #pragma unroll
    for (int q = 0; q < 16; q++) {
        float4 w = __ldg(cr + q);
        int c = q * 4;
        B = fmaf(tokp[(c + 0) * TOK + t], w.x, B);
        B = fmaf(tokp[(c + 1) * TOK + t], w.y, B);
        B = fmaf(tokp[(c + 2) * TOK + t], w.z, B);
        B = fmaf(tokp[(c + 3) * TOK + t], w.w, B);
    }
    return __fadd_rn(__fmaf_rn(-2.0f, B, A), scn[s]);
}

// ---------------- prep ----------------
// cnorm threads first (gid < S): latency-critical serial chain starts with
// all 16 row loads already in flight (MLP=16). Rounding order unchanged.
__global__ void vq_prep_kernel(const float* __restrict__ codebook) {
    int gid = blockIdx.x * blockDim.x + threadIdx.x;

    if (gid < S) {
        const float4* row = (const float4*)(codebook + gid * C);
        float4 rv[16];
        #pragma unroll
        for (int q = 0; q < 16; q++) rv[q] = __ldg(row + q);
        float acc = 0.f;
        #pragma unroll
        for (int q = 0; q < 16; q++) {
            acc = __fadd_rn(acc, __fmul_rn(rv[q].x, rv[q].x));
            acc = __fadd_rn(acc, __fmul_rn(rv[q].y, rv[q].y));
            acc = __fadd_rn(acc, __fmul_rn(rv[q].z, rv[q].z));
            acc = __fadd_rn(acc, __fmul_rn(rv[q].w, rv[q].w));
        }
        g_cnorm[gid] = acc;
        g_counts[gid] = 0.f;
        if (gid == 0) g_loss = 0.f;
    }

    int v = gid - S;
    if (v >= 0 && v < S * C / 4) {
        float4 c4 = ((const float4*)codebook)[v];
        __nv_bfloat162 q0 = __floats2bfloat162_rn(c4.x, c4.y);
        __nv_bfloat162 q1 = __floats2bfloat162_rn(c4.z, c4.w);
        uint2 wv;
        wv.x = *(unsigned*)&q0; wv.y = *(unsigned*)&q1;
        ((uint2*)g_cbBf)[v] = wv;
        ((float4*)g_dw)[v] = make_float4(0.f, 0.f, 0.f, 0.f);
    }
}

// ---------------- main ----------------
__global__ void __launch_bounds__(TPB, 2)
vq_main_kernel(const float* __restrict__ x,
               const float* __restrict__ codebook,
               float* __restrict__ outp) {
    extern __shared__ char smc[];
    float* tok  = (float*)(smc + SMB_TOK);
    float* scr  = (float*)(smc + SMB_A);     // fp32 view of A/B union (xq tile)
    float* scn  = (float*)(smc + SMB_SCN);
    float* stn2 = (float*)(smc + SMB_STN);
    unsigned* sgmin = (unsigned*)(smc + SMB_GMIN);
    float* sthr = (float*)(smc + SMB_THR);
    int*   sbi  = (int*)(smc + SMB_SBI);
    int*   scand= (int*)(smc + SMB_CND);
    int*   scnt = (int*)(smc + SMB_CNT);
    float* pbv  = (float*)(smc + SMB_PBV);
    int*   pbi  = (int*)(smc + SMB_PBI);
    float* sred = (float*)(smc + SMB_RED);
    unsigned* smaxb = (unsigned*)(smc + SMB_SMAX);

    const unsigned sbase = smem_u32(smc);
    const int tid  = threadIdx.x;
    const int w    = tid >> 5;
    const int lane = tid & 31;
    const int tw   = w & 3;        // token tile (32 tokens)
    const int sw   = w >> 2;       // code half within each round
    const int b    = blockIdx.x;
    const int n    = b >> 5;
    const int p0   = (b & 31) * TOK;
    const float* xb = x + (size_t)n * C * P + p0;

    if (tid == 0) *smaxb = 0;
    if (tid < TOK) { scnt[tid] = 0; sgmin[tid] = 0xffffffffu; }
    __syncthreads();

    // code norms + block max
    {
        float mx = 0.f;
        for (int i = tid; i < S; i += TPB) {
            float v = g_cnorm[i];
            scn[i] = v;
            mx = fmaxf(mx, v);
        }
        atomicMax((int*)smaxb, __float_as_int(mx));
    }

    // x tile fp32 [c][t]
    for (int v = tid; v < C * TOK / 4; v += TPB) {
        int c = v >> 5, q = v & 31;
        *(float4*)(tok + c * TOK + q * 4) = *(const float4*)(xb + c * P + q * 4);
    }
    __syncthreads();

    // token norms (reference rounding)
    if (tid < TOK) {
        float a = 0.f;
        #pragma unroll
        for (int c = 0; c < C; c++) {
            float v = tok[c * TOK + tid];
            a = __fadd_rn(a, __fmul_rn(v, v));
        }
        stn2[tid] = a;
    }

    // convert A tile to bf16 [t][k], 128B SW128 rows
    {
        int t = tid >> 1, half = tid & 1, k0 = half * 32;
        #pragma unroll
        for (int q = 0; q < 4; q++) {
            unsigned u[4];
            #pragma unroll
            for (int j = 0; j < 4; j++) {
                int k = k0 + q * 8 + j * 2;
                __nv_bfloat162 pr = __floats2bfloat162_rn(tok[k * TOK + t], tok[(k + 1) * TOK + t]);
                u[j] = *(unsigned*)&pr;
            }
            unsigned byte = (unsigned)(t * 128 + half * 64 + q * 16);
            *(uint4*)(smc + SMB_A + SW128(byte)) = make_uint4(u[0], u[1], u[2], u[3]);
        }
    }
    __syncthreads();

    // A fragments: 2 m-tiles (32 tokens) x 64 k per warp
    unsigned afr[2][4][4];
    #pragma unroll
    for (int mi = 0; mi < 2; mi++)
        #pragma unroll
        for (int kc = 0; kc < 4; kc++) {
            unsigned byte = (unsigned)((tw * 32 + mi * 16 + (lane & 15)) * 128 + kc * 32 + (lane >> 4) * 16);
            ldmx4(afr[mi][kc][0], afr[mi][kc][1], afr[mi][kc][2], afr[mi][kc][3],
                  sbase + SMB_A + SW128(byte));
        }

    // hoisted B-fragment x4 addresses. ldmatrix.x4 loads 4 m8n8 matrices from
    // 4 lane-quadrant addresses; quadrant q -> (kc = kcbase + (q>>1), khalf = q&1)
    // giving regs {kcA.b0, kcA.b1, kcB.b0, kcB.b1}. The SW128 xor depends only on
    // row&7 = lane&7 (jt-invariant), so per-jt step stays +1024 bytes linear.
    unsigned baddr4[2];
    {
        int q = lane >> 3;
        #pragma unroll
        for (int pr = 0; pr < 2; pr++) {
            int kc = pr * 2 + (q >> 1);
            unsigned byte = (unsigned)(sw * 16384 + (lane & 7) * 128 + kc * 32 + (q & 1) * 16);
            baddr4[pr] = sbase + SMB_B + SW128(byte);
        }
    }

    const int g  = lane >> 2;      // fragment row group
    const int qq = lane & 3;       // fragment col pair
    const int t0 = tw * 32 + g;    // token rows: t0, t0+8, t0+16, t0+24
    const float smax = __int_as_float(*(int*)smaxb);

    // ---- scan 1: screened global min per token ----
    {
        float rmin[4] = {3.4e38f, 3.4e38f, 3.4e38f, 3.4e38f};
        for (int r = 0; r < 2; r++) {
            // stage 256 codes (two 16KB subtiles)
            for (int task = tid; task < 512; task += TPB) {
                int row = task >> 1, half = task & 1;
                const uint4* src = g_cbBf + (r * 256 + row) * 8 + half * 4;
                #pragma unroll
                for (int q = 0; q < 4; q++) {
                    unsigned byte = (unsigned)(row * 128 + half * 64 + q * 16);
                    *(uint4*)(smc + SMB_B + SW128(byte)) = src[q];
                }
            }
            __syncthreads();
            #pragma unroll 2
            for (int jt = 0; jt < 16; jt++) {
                unsigned bfr[4][2];
                ldmx4(bfr[0][0], bfr[0][1], bfr[1][0], bfr[1][1], baddr4[0] + (unsigned)jt * 1024);
                ldmx4(bfr[2][0], bfr[2][1], bfr[3][0], bfr[3][1], baddr4[1] + (unsigned)jt * 1024);
                // split accumulators: 4 independent chains of depth 2
                float d0A[4] = {0,0,0,0}, d0B[4] = {0,0,0,0};
                float d1A[4] = {0,0,0,0}, d1B[4] = {0,0,0,0};
                mma_bf16(d0A, afr[0][0], bfr[0]);
                mma_bf16(d1A, afr[1][0], bfr[0]);
                mma_bf16(d0B, afr[0][1], bfr[1]);
                mma_bf16(d1B, afr[1][1], bfr[1]);
                mma_bf16(d0A, afr[0][2], bfr[2]);
                mma_bf16(d1A, afr[1][2], bfr[2]);
                mma_bf16(d0B, afr[0][3], bfr[3]);
                mma_bf16(d1B, afr[1][3], bfr[3]);

                int s0 = r * 256 + sw * 128 + jt * 8 + qq * 2;
                float cn0 = scn[s0], cn1 = scn[s0 + 1];
                rmin[0] = fminf(rmin[0], fminf(__fmaf_rn(-2.f, d0A[0] + d0B[0], cn0),
                                               __fmaf_rn(-2.f, d0A[1] + d0B[1], cn1)));
                rmin[1] = fminf(rmin[1], fminf(__fmaf_rn(-2.f, d0A[2] + d0B[2], cn0),
                                               __fmaf_rn(-2.f, d0A[3] + d0B[3], cn1)));
                rmin[2] = fminf(rmin[2], fminf(__fmaf_rn(-2.f, d1A[0] + d1B[0], cn0),
                                               __fmaf_rn(-2.f, d1A[1] + d1B[1], cn1)));
                rmin[3] = fminf(rmin[3], fminf(__fmaf_rn(-2.f, d1A[2] + d1B[2], cn0),
                                               __fmaf_rn(-2.f, d1A[3] + d1B[3], cn1)));
            }
            __syncthreads();
        }
        #pragma unroll
        for (int i = 0; i < 4; i++) {
            rmin[i] = fminf(rmin[i], __shfl_xor_sync(0xffffffffu, rmin[i], 1));
            rmin[i] = fminf(rmin[i], __shfl_xor_sync(0xffffffffu, rmin[i], 2));
        }
        if (qq == 0) {
            atomicMin(&sgmin[t0],      fkey(rmin[0]));
            atomicMin(&sgmin[t0 + 8],  fkey(rmin[1]));
            atomicMin(&sgmin[t0 + 16], fkey(rmin[2]));
            atomicMin(&sgmin[t0 + 24], fkey(rmin[3]));
        }
    }
    __syncthreads();

    // capture thresholds: final gmin + margin (2x bf16 dot error bound + 25%)
    if (tid < TOK)
        sthr[tid] = fdec(sgmin[tid]) + 1.25f * 0.03125f * sqrtf(stn2[tid] * smax) + 1e-5f;
    __syncthreads();

    // ---- scan 2: capture candidates vs final threshold ----
    // process r=1 FIRST: codes 256..511 are still resident in the B tile from
    // scan 1's last round (no writes to B since), so one staging is skipped.
    {
        const float thr0 = sthr[t0], thr1 = sthr[t0 + 8], thr2 = sthr[t0 + 16], thr3 = sthr[t0 + 24];
        #pragma unroll
        for (int rr = 0; rr < 2; rr++) {
            const int r = 1 - rr;              // r=1 (resident) then r=0
            if (rr == 1) {
                for (int task = tid; task < 512; task += TPB) {
                    int row = task >> 1, half = task & 1;
                    const uint4* src = g_cbBf + (r * 256 + row) * 8 + half * 4;
                    #pragma unroll
                    for (int q = 0; q < 4; q++) {
                        unsigned byte = (unsigned)(row * 128 + half * 64 + q * 16);
                        *(uint4*)(smc + SMB_B + SW128(byte)) = src[q];
                    }
                }
                __syncthreads();
            }
            #pragma unroll 2
            for (int jt = 0; jt < 16; jt++) {
                unsigned bfr[4][2];
                ldmx4(bfr[0][0], bfr[0][1], bfr[1][0], bfr[1][1], baddr4[0] + (unsigned)jt * 1024);
                ldmx4(bfr[2][0], bfr[2][1], bfr[3][0], bfr[3][1], baddr4[1] + (unsigned)jt * 1024);
                float d0A[4] = {0,0,0,0}, d0B[4] = {0,0,0,0};
                float d1A[4] = {0,0,0,0}, d1B[4] = {0,0,0,0};
                mma_bf16(d0A, afr[0][0], bfr[0]);
                mma_bf16(d1A, afr[1][0], bfr[0]);
                mma_bf16(d0B, afr[0][1], bfr[1]);
                mma_bf16(d1B, afr[1][1], bfr[1]);
                mma_bf16(d0A, afr[0][2], bfr[2]);
                mma_bf16(d1A, afr[1][2], bfr[2]);
                mma_bf16(d0B, afr[0][3], bfr[3]);
                mma_bf16(d1B, afr[1][3], bfr[3]);

                int s0 = r * 256 + sw * 128 + jt * 8 + qq * 2;
                float cn0 = scn[s0], cn1 = scn[s0 + 1];
                float v;
                v = __fmaf_rn(-2.f, d0A[0] + d0B[0], cn0);
                if (v <= thr0) { int sl = atomicAdd(&scnt[t0], 1); if (sl < CAND) scand[t0 * CAND + sl] = s0; }
                v = __fmaf_rn(-2.f, d0A[1] + d0B[1], cn1);
                if (v <= thr0) { int sl = atomicAdd(&scnt[t0], 1); if (sl < CAND) scand[t0 * CAND + sl] = s0 + 1; }
                v = __fmaf_rn(-2.f, d0A[2] + d0B[2], cn0);
                if (v <= thr1) { int sl = atomicAdd(&scnt[t0 + 8], 1); if (sl < CAND) scand[(t0 + 8) * CAND + sl] = s0; }
                v = __fmaf_rn(-2.f, d0A[3] + d0B[3], cn1);
                if (v <= thr1) { int sl = atomicAdd(&scnt[t0 + 8], 1); if (sl < CAND) scand[(t0 + 8) * CAND + sl] = s0 + 1; }
                v = __fmaf_rn(-2.f, d1A[0] + d1B[0], cn0);
                if (v <= thr2) { int sl = atomicAdd(&scnt[t0 + 16], 1); if (sl < CAND) scand[(t0 + 16) * CAND + sl] = s0; }
                v = __fmaf_rn(-2.f, d1A[1] + d1B[1], cn1);
                if (v <= thr2) { int sl = atomicAdd(&scnt[t0 + 16], 1); if (sl < CAND) scand[(t0 + 16) * CAND + sl] = s0 + 1; }
                v = __fmaf_rn(-2.f, d1A[2] + d1B[2], cn0);
                if (v <= thr3) { int sl = atomicAdd(&scnt[t0 + 24], 1); if (sl < CAND) scand[(t0 + 24) * CAND + sl] = s0; }
                v = __fmaf_rn(-2.f, d1A[3] + d1B[3], cn1);
                if (v <= thr3) { int sl = atomicAdd(&scnt[t0 + 24], 1); if (sl < CAND) scand[(t0 + 24) * CAND + sl] = s0 + 1; }
            }
            __syncthreads();
        }
    }

    // ---- exact rescore (2 threads per token) ----
    {
        int t = tid & 127;
        int half = tid >> 7;
        float A = stn2[t];
        float bestd = 3.4e38f;
        int bests = 1 << 30;
        int cnt = scnt[t];
        if (cnt <= CAND) {
            for (int i = half; i < cnt; i += 2) {
                int s = scand[t * CAND + i];
                float d = rescore_one(tok, t, s, A, scn, codebook);
                if (d < bestd || (d == bestd && s < bests)) { bestd = d; bests = s; }
            }
        } else {
            for (int s = half; s < S; s += 2) {
                float d = rescore_one(tok, t, s, A, scn, codebook);
                if (d < bestd || (d == bestd && s < bests)) { bestd = d; bests = s; }
            }
        }
        pbv[tid] = bestd;
        pbi[tid] = bests;
    }
    __syncthreads();
    if (tid < TOK) {
        float d1 = pbv[tid];       int s1 = pbi[tid];
        float d2 = pbv[tid + 128]; int s2 = pbi[tid + 128];
        int bs = (d2 < d1 || (d2 == d1 && s2 < s1)) ? s2 : s1;
        sbi[tid] = bs;
        outp[OFF_IDX + (size_t)n * P + p0 + tid] = (float)bs;
        atomicAdd(&g_counts[bs], 1.0f);
    }
    __syncthreads();

    // gather xq into scr[c][t] (overwrites A/B tiles) + dw scatter
    {
        int t = tid >> 1, c0 = (tid & 1) * 32;
        int sdx = sbi[t];
        const float4* crow = (const float4*)(codebook + sdx * C + c0);
        #pragma unroll
        for (int q = 0; q < 8; q++) {
            float4 v = crow[q];
            int c = c0 + q * 4;
            scr[(c + 0) * TOK + t] = v.x;
            scr[(c + 1) * TOK + t] = v.y;
            scr[(c + 2) * TOK + t] = v.z;
            scr[(c + 3) * TOK + t] = v.w;
        }
        float* dwrow = g_dw + sdx * C + c0;
        #pragma unroll 8
        for (int j = 0; j < 32; j++)
            atomicAdd(&dwrow[j], tok[(c0 + j) * TOK + t]);
    }
    __syncthreads();

    // straight-through out + commitment loss
    float lsum = 0.f;
    float* ob = outp + OFF_OUT + (size_t)n * C * P + p0;
    for (int v = tid; v < C * TOK; v += TPB) {
        int c = v >> 7, t = v & 127;
        float xv = tok[c * TOK + t];
        float qv = scr[c * TOK + t];
        ob[c * P + t] = xv + (qv - xv);
        float dd = xv - qv;
        lsum = fmaf(dd, dd, lsum);
    }
    #pragma unroll
    for (int d = 16; d >= 1; d >>= 1) lsum += __shfl_xor_sync(0xffffffffu, lsum, d);
    if (lane == 0) sred[w] = lsum;
    __syncthreads();
    if (tid == 0) {
        float tot = 0.f;
        #pragma unroll
        for (int q = 0; q < TPB / 32; q++) tot += sred[q];
        atomicAdd(&g_loss, tot);
    }
}

// ---------------- finalize: 64 blocks, each redundantly reduces nsum ----------------
__global__ void vq_finalize_kernel(const float* __restrict__ ema_w,
                                   const float* __restrict__ cluster_size,
                                   const int* __restrict__ steps_p,
                                   float* __restrict__ outp) {
    __shared__ float sred[S];
    int t = threadIdx.x;          // 0..511

    int st = steps_p[0];
    if (st <= 0 || st > 1000000000) {
        float f = __int_as_float(st);
        st = (f > 0.5f && f < 1e9f) ? (int)(f + 0.5f) : 1;
    }
    float bias_corr = (float)(1.0 - pow(0.99, (double)st));

    float cs_new_t = 0.99f * cluster_size[t] + 0.01f * g_counts[t];
    float cs_bc_t  = cs_new_t / bias_corr;
    sred[t] = cs_bc_t;
    if (blockIdx.x == 0) outp[OFF_CS + t] = cs_new_t;
    __syncthreads();
    #pragma unroll
    for (int d = 256; d >= 1; d >>= 1) {
        if (t < d) sred[t] += sred[t + d];
        __syncthreads();
    }
    float nsum = sred[0];

    // this block's 8 codes x 64 channels
    int sc = blockIdx.x * 8 + (t >> 6);
    int c  = t & 63;
    float cs_bc_s = (0.99f * cluster_size[sc] + 0.01f * g_counts[sc]) / bias_corr;
    float upd = (cs_bc_s + 1e-7f) / (nsum + (float)S * 1e-7f) * nsum;
    int i = sc * C + c;
    float ew = 0.99f * ema_w[i] + 0.01f * g_dw[i];
    outp[OFF_EW + i]  = ew;
    outp[OFF_NCB + i] = (ew / bias_corr) / upd;

    if (blockIdx.x == 0 && t == 0) outp[OFF_LOSS] = g_loss / 8388608.0f;
}

// ---------------- launch ----------------
extern "C" void kernel_launch(void* const* d_in, const int* in_sizes, int n_in,
                              void* d_out, int out_size) {
    const float* x            = (const float*)d_in[0];
    const float* codebook     = (const float*)d_in[1];
    const float* ema_w        = (const float*)d_in[2];
    const float* cluster_size = (const float*)d_in[3];
    const int*   steps        = (const int*)d_in[4];
    float* outp = (float*)d_out;

    cudaFuncSetAttribute(vq_main_kernel,
                         cudaFuncAttributeMaxDynamicSharedMemorySize, SMEM_BYTES);

    vq_prep_kernel<<<64, 256>>>(codebook);
    vq_main_kernel<<<NTOK / TOK, TPB, SMEM_BYTES>>>(x, codebook, outp);
    vq_finalize_kernel<<<64, 512>>>(ema_w, cluster_size, steps, outp);
}

// round 17
// speedup vs baseline: 1.9620x; 1.0698x over previous
#include <cuda_runtime.h>
#include <cuda_bf16.h>
#include <cstdint>
#include <math.h>

#define C     64
#define S     512
#define P     4096
#define NB    32
#define NTOK  (NB * P)          // 131072
#define TOK   128               // tokens per block
#define TPB   256
#define CAND  16

// output layout (float32, tuple flattened in order)
#define OFF_LOSS 0
#define OFF_IDX  1
#define OFF_OUT  (OFF_IDX + NTOK)
#define OFF_NCB  (OFF_OUT + NTOK * C)
#define OFF_CS   (OFF_NCB + S * C)
#define OFF_EW   (OFF_CS + S)

// smem byte layout
#define SMB_TOK   0              // fp32 tok[C][TOK]        32768
#define SMB_A     32768          // bf16 A[128][64]         16384 } union: fp32 xq[C][TOK]
#define SMB_B     49152          // bf16 B[256][64] x2 subtiles 32768 }
#define SMB_SCN   81920          // fp32 [S]                 2048
#define SMB_STN   83968          // fp32 [TOK]                512
#define SMB_GMIN  84480          // u32  [TOK] ordered keys   512
#define SMB_THR   84992          // fp32 [TOK]                512
#define SMB_SBI   85504          // int  [TOK]                512
#define SMB_CND   86016          // int  [TOK][CAND]         8192
#define SMB_CNT   94208          // int  [TOK]                512
#define SMB_PBV   94720          // fp32 [TPB]               1024
#define SMB_PBI   95744          // int  [TPB]               1024
#define SMB_RED   96768          // fp32 [8]                   32
#define SMB_SMAX  96800          // u32                         4
#define SMEM_BYTES 96832

#define SW128(b) ((b) ^ (((b) >> 3) & 0x70))

// ---------------- device scratch ----------------
__device__ float g_counts[S];
__device__ float g_dw[S * C];
__device__ float g_cnorm[S];
__device__ float g_loss;
// bf16 codebook stored PRE-SWIZZLED in the exact smem image layout:
// subtile r (codes r*256..r*256+255) occupies bytes [r*32768, (r+1)*32768),
// with byte off placed at SW128(off). Main staging = pure linear copy.
__device__ uint4 g_cbSw[4096];   // 64KB

// ---------------- helpers ----------------
__device__ __forceinline__ unsigned smem_u32(const void* p) {
    unsigned a;
    asm("{ .reg .u64 t; cvta.to.shared.u64 t, %1; cvt.u32.u64 %0, t; }" : "=r"(a) : "l"(p));
    return a;
}
__device__ __forceinline__ void ldmx4(unsigned& r0, unsigned& r1, unsigned& r2, unsigned& r3,
                                      unsigned addr) {
    asm volatile("ldmatrix.sync.aligned.m8n8.x4.shared.b16 {%0,%1,%2,%3}, [%4];"
                 : "=r"(r0), "=r"(r1), "=r"(r2), "=r"(r3) : "r"(addr));
}
__device__ __forceinline__ void mma_bf16(float* d, const unsigned* a, const unsigned* b) {
    asm volatile("mma.sync.aligned.m16n8k16.row.col.f32.bf16.bf16.f32 "
                 "{%0,%1,%2,%3}, {%4,%5,%6,%7}, {%8,%9}, {%0,%1,%2,%3};"
                 : "+f"(d[0]), "+f"(d[1]), "+f"(d[2]), "+f"(d[3])
                 : "r"(a[0]), "r"(a[1]), "r"(a[2]), "r"(a[3]), "r"(b[0]), "r"(b[1]));
}
// ordered-int encode/decode for float atomicMin over any-sign floats
__device__ __forceinline__ unsigned fkey(float f) {
    unsigned b = __float_as_uint(f);
    return b ^ ((b & 0x80000000u) ? 0xffffffffu : 0x80000000u);
}
__device__ __forceinline__ float fdec(unsigned k) {
    unsigned b = (k & 0x80000000u) ? (k ^ 0x80000000u) : ~k;
    return __uint_as_float(b);
}

// exact reference-lattice distance for (token t, code s)
__device__ __forceinline__ float rescore_one(const float* tokp, int t, int s, float A,
                                             const float* scn, const float* codebook) {
    const float4* cr = (const float4*)(codebook + s * C);
    float B = 0.f;
    #pragma unroll
    for (int q = 0; q < 16; q++) {
        float4 w = __ldg(cr + q);
        int c = q * 4;
        B = fmaf(tokp[(c + 0) * TOK + t], w.x, B);
        B = fmaf(tokp[(c + 1) * TOK + t], w.y, B);
        B = fmaf(tokp[(c + 2) * TOK + t], w.z, B);
        B = fmaf(tokp[(c + 3) * TOK + t], w.w, B);
    }
    return __fadd_rn(__fmaf_rn(-2.0f, B, A), scn[s]);
}

// ---------------- prep ----------------
// cnorm threads first (gid < S): latency-critical serial chain with MLP=16.
// Convert threads write the bf16 codebook PRE-SWIZZLED (smem image layout).
__global__ void vq_prep_kernel(const float* __restrict__ codebook) {
    int gid = blockIdx.x * blockDim.x + threadIdx.x;

    if (gid < S) {
        const float4* row = (const float4*)(codebook + gid * C);
        float4 rv[16];
        #pragma unroll
        for (int q = 0; q < 16; q++) rv[q] = __ldg(row + q);
        float acc = 0.f;
        #pragma unroll
        for (int q = 0; q < 16; q++) {
            acc = __fadd_rn(acc, __fmul_rn(rv[q].x, rv[q].x));
            acc = __fadd_rn(acc, __fmul_rn(rv[q].y, rv[q].y));
            acc = __fadd_rn(acc, __fmul_rn(rv[q].z, rv[q].z));
            acc = __fadd_rn(acc, __fmul_rn(rv[q].w, rv[q].w));
        }
        g_cnorm[gid] = acc;
        g_counts[gid] = 0.f;
        if (gid == 0) g_loss = 0.f;
    }

    int v = gid - S;
    if (v >= 0 && v < S * C / 4) {      // v indexes 8-byte bf16 chunks (8192 total)
        float4 c4 = ((const float4*)codebook)[v];
        __nv_bfloat162 q0 = __floats2bfloat162_rn(c4.x, c4.y);
        __nv_bfloat162 q1 = __floats2bfloat162_rn(c4.z, c4.w);
        uint2 wv;
        wv.x = *(unsigned*)&q0; wv.y = *(unsigned*)&q1;
        unsigned gbyte = (unsigned)v * 8u;
        unsigned r     = gbyte >> 15;           // 32KB subtile
        unsigned off   = gbyte & 32767u;
        *(uint2*)((char*)g_cbSw + r * 32768u + SW128(off)) = wv;
        ((float4*)g_dw)[v] = make_float4(0.f, 0.f, 0.f, 0.f);
    }
}

// ---------------- main ----------------
__global__ void __launch_bounds__(TPB, 2)
vq_main_kernel(const float* __restrict__ x,
               const float* __restrict__ codebook,
               float* __restrict__ outp) {
    extern __shared__ char smc[];
    float* tok  = (float*)(smc + SMB_TOK);
    float* scr  = (float*)(smc + SMB_A);     // fp32 view of A/B union (xq tile)
    float* scn  = (float*)(smc + SMB_SCN);
    float* stn2 = (float*)(smc + SMB_STN);
    unsigned* sgmin = (unsigned*)(smc + SMB_GMIN);
    float* sthr = (float*)(smc + SMB_THR);
    int*   sbi  = (int*)(smc + SMB_SBI);
    int*   scand= (int*)(smc + SMB_CND);
    int*   scnt = (int*)(smc + SMB_CNT);
    float* pbv  = (float*)(smc + SMB_PBV);
    int*   pbi  = (int*)(smc + SMB_PBI);
    float* sred = (float*)(smc + SMB_RED);
    unsigned* smaxb = (unsigned*)(smc + SMB_SMAX);

    const unsigned sbase = smem_u32(smc);
    const int tid  = threadIdx.x;
    const int w    = tid >> 5;
    const int lane = tid & 31;
    const int tw   = w & 3;        // token tile (32 tokens)
    const int sw   = w >> 2;       // code half within each round
    const int b    = blockIdx.x;
    const int n    = b >> 5;
    const int p0   = (b & 31) * TOK;
    const float* xb = x + (size_t)n * C * P + p0;

    if (tid == 0) *smaxb = 0;
    if (tid < TOK) { scnt[tid] = 0; sgmin[tid] = 0xffffffffu; }
    __syncthreads();

    // code norms + block max
    {
        float mx = 0.f;
        for (int i = tid; i < S; i += TPB) {
            float v = g_cnorm[i];
            scn[i] = v;
            mx = fmaxf(mx, v);
        }
        atomicMax((int*)smaxb, __float_as_int(mx));
    }

    // x tile fp32 [c][t]
    for (int v = tid; v < C * TOK / 4; v += TPB) {
        int c = v >> 5, q = v & 31;
        *(float4*)(tok + c * TOK + q * 4) = *(const float4*)(xb + c * P + q * 4);
    }
    __syncthreads();

    // token norms (reference rounding)
    if (tid < TOK) {
        float a = 0.f;
        #pragma unroll
        for (int c = 0; c < C; c++) {
            float v = tok[c * TOK + tid];
            a = __fadd_rn(a, __fmul_rn(v, v));
        }
        stn2[tid] = a;
    }

    // convert A tile to bf16 [t][k], 128B SW128 rows
    {
        int t = tid >> 1, half = tid & 1, k0 = half * 32;
        #pragma unroll
        for (int q = 0; q < 4; q++) {
            unsigned u[4];
            #pragma unroll
            for (int j = 0; j < 4; j++) {
                int k = k0 + q * 8 + j * 2;
                __nv_bfloat162 pr = __floats2bfloat162_rn(tok[k * TOK + t], tok[(k + 1) * TOK + t]);
                u[j] = *(unsigned*)&pr;
            }
            unsigned byte = (unsigned)(t * 128 + half * 64 + q * 16);
            *(uint4*)(smc + SMB_A + SW128(byte)) = make_uint4(u[0], u[1], u[2], u[3]);
        }
    }
    __syncthreads();

    // A fragments: 2 m-tiles (32 tokens) x 64 k per warp
    unsigned afr[2][4][4];
    #pragma unroll
    for (int mi = 0; mi < 2; mi++)
        #pragma unroll
        for (int kc = 0; kc < 4; kc++) {
            unsigned byte = (unsigned)((tw * 32 + mi * 16 + (lane & 15)) * 128 + kc * 32 + (lane >> 4) * 16);
            ldmx4(afr[mi][kc][0], afr[mi][kc][1], afr[mi][kc][2], afr[mi][kc][3],
                  sbase + SMB_A + SW128(byte));
        }

    // hoisted B-fragment x4 addresses (quadrant q -> kc = base+(q>>1), khalf = q&1);
    // SW128 xor depends only on lane&7 (jt-invariant), per-jt step +1024B linear.
    unsigned baddr4[2];
    {
        int q = lane >> 3;
        #pragma unroll
        for (int pr = 0; pr < 2; pr++) {
            int kc = pr * 2 + (q >> 1);
            unsigned byte = (unsigned)(sw * 16384 + (lane & 7) * 128 + kc * 32 + (q & 1) * 16);
            baddr4[pr] = sbase + SMB_B + SW128(byte);
        }
    }

    const int g  = lane >> 2;      // fragment row group
    const int qq = lane & 3;       // fragment col pair
    const int t0 = tw * 32 + g;    // token rows: t0, t0+8, t0+16, t0+24
    const float smax = __int_as_float(*(int*)smaxb);

    uint4* bdst = (uint4*)(smc + SMB_B);

    // ---- scan 1: screened global min per token ----
    {
        float rmin[4] = {3.4e38f, 3.4e38f, 3.4e38f, 3.4e38f};
        for (int r = 0; r < 2; r++) {
            // stage 256 codes: pure linear copy of the pre-swizzled image
            {
                const uint4* src = g_cbSw + r * 2048;
                #pragma unroll
                for (int i = 0; i < 2048 / TPB; i++)
                    bdst[tid + i * TPB] = __ldg(src + tid + i * TPB);
            }
            __syncthreads();
            #pragma unroll 2
            for (int jt = 0; jt < 16; jt++) {
                unsigned bfr[4][2];
                ldmx4(bfr[0][0], bfr[0][1], bfr[1][0], bfr[1][1], baddr4[0] + (unsigned)jt * 1024);
                ldmx4(bfr[2][0], bfr[2][1], bfr[3][0], bfr[3][1], baddr4[1] + (unsigned)jt * 1024);
                // split accumulators: 4 independent chains of depth 2
                float d0A[4] = {0,0,0,0}, d0B[4] = {0,0,0,0};
                float d1A[4] = {0,0,0,0}, d1B[4] = {0,0,0,0};
                mma_bf16(d0A, afr[0][0], bfr[0]);
                mma_bf16(d1A, afr[1][0], bfr[0]);
                mma_bf16(d0B, afr[0][1], bfr[1]);
                mma_bf16(d1B, afr[1][1], bfr[1]);
                mma_bf16(d0A, afr[0][2], bfr[2]);
                mma_bf16(d1A, afr[1][2], bfr[2]);
                mma_bf16(d0B, afr[0][3], bfr[3]);
                mma_bf16(d1B, afr[1][3], bfr[3]);

                int s0 = r * 256 + sw * 128 + jt * 8 + qq * 2;
                float cn0 = scn[s0], cn1 = scn[s0 + 1];
                rmin[0] = fminf(rmin[0], fminf(__fmaf_rn(-2.f, d0A[0] + d0B[0], cn0),
                                               __fmaf_rn(-2.f, d0A[1] + d0B[1], cn1)));
                rmin[1] = fminf(rmin[1], fminf(__fmaf_rn(-2.f, d0A[2] + d0B[2], cn0),
                                               __fmaf_rn(-2.f, d0A[3] + d0B[3], cn1)));
                rmin[2] = fminf(rmin[2], fminf(__fmaf_rn(-2.f, d1A[0] + d1B[0], cn0),
                                               __fmaf_rn(-2.f, d1A[1] + d1B[1], cn1)));
                rmin[3] = fminf(rmin[3], fminf(__fmaf_rn(-2.f, d1A[2] + d1B[2], cn0),
                                               __fmaf_rn(-2.f, d1A[3] + d1B[3], cn1)));
            }
            __syncthreads();
        }
        #pragma unroll
        for (int i = 0; i < 4; i++) {
            rmin[i] = fminf(rmin[i], __shfl_xor_sync(0xffffffffu, rmin[i], 1));
            rmin[i] = fminf(rmin[i], __shfl_xor_sync(0xffffffffu, rmin[i], 2));
        }
        if (qq == 0) {
            atomicMin(&sgmin[t0],      fkey(rmin[0]));
            atomicMin(&sgmin[t0 + 8],  fkey(rmin[1]));
            atomicMin(&sgmin[t0 + 16], fkey(rmin[2]));
            atomicMin(&sgmin[t0 + 24], fkey(rmin[3]));
        }
    }
    __syncthreads();

    // capture thresholds: final gmin + margin (2x bf16 dot error bound + 25%)
    if (tid < TOK)
        sthr[tid] = fdec(sgmin[tid]) + 1.25f * 0.03125f * sqrtf(stn2[tid] * smax) + 1e-5f;
    __syncthreads();

    // ---- scan 2: capture candidates vs final threshold ----
    // process r=1 FIRST (codes 256..511 still resident in B) then stage r=0.
    {
        const float thr0 = sthr[t0], thr1 = sthr[t0 + 8], thr2 = sthr[t0 + 16], thr3 = sthr[t0 + 24];
        #pragma unroll
        for (int rr = 0; rr < 2; rr++) {
            const int r = 1 - rr;
            if (rr == 1) {
                const uint4* src = g_cbSw + r * 2048;
                #pragma unroll
                for (int i = 0; i < 2048 / TPB; i++)
                    bdst[tid + i * TPB] = __ldg(src + tid + i * TPB);
                __syncthreads();
            }
            #pragma unroll 2
            for (int jt = 0; jt < 16; jt++) {
                unsigned bfr[4][2];
                ldmx4(bfr[0][0], bfr[0][1], bfr[1][0], bfr[1][1], baddr4[0] + (unsigned)jt * 1024);
                ldmx4(bfr[2][0], bfr[2][1], bfr[3][0], bfr[3][1], baddr4[1] + (unsigned)jt * 1024);
                float d0A[4] = {0,0,0,0}, d0B[4] = {0,0,0,0};
                float d1A[4] = {0,0,0,0}, d1B[4] = {0,0,0,0};
                mma_bf16(d0A, afr[0][0], bfr[0]);
                mma_bf16(d1A, afr[1][0], bfr[0]);
                mma_bf16(d0B, afr[0][1], bfr[1]);
                mma_bf16(d1B, afr[1][1], bfr[1]);
                mma_bf16(d0A, afr[0][2], bfr[2]);
                mma_bf16(d1A, afr[1][2], bfr[2]);
                mma_bf16(d0B, afr[0][3], bfr[3]);
                mma_bf16(d1B, afr[1][3], bfr[3]);

                int s0 = r * 256 + sw * 128 + jt * 8 + qq * 2;
                float cn0 = scn[s0], cn1 = scn[s0 + 1];
                float v;
                v = __fmaf_rn(-2.f, d0A[0] + d0B[0], cn0);
                if (v <= thr0) { int sl = atomicAdd(&scnt[t0], 1); if (sl < CAND) scand[t0 * CAND + sl] = s0; }
                v = __fmaf_rn(-2.f, d0A[1] + d0B[1], cn1);
                if (v <= thr0) { int sl = atomicAdd(&scnt[t0], 1); if (sl < CAND) scand[t0 * CAND + sl] = s0 + 1; }
                v = __fmaf_rn(-2.f, d0A[2] + d0B[2], cn0);
                if (v <= thr1) { int sl = atomicAdd(&scnt[t0 + 8], 1); if (sl < CAND) scand[(t0 + 8) * CAND + sl] = s0; }
                v = __fmaf_rn(-2.f, d0A[3] + d0B[3], cn1);
                if (v <= thr1) { int sl = atomicAdd(&scnt[t0 + 8], 1); if (sl < CAND) scand[(t0 + 8) * CAND + sl] = s0 + 1; }
                v = __fmaf_rn(-2.f, d1A[0] + d1B[0], cn0);
                if (v <= thr2) { int sl = atomicAdd(&scnt[t0 + 16], 1); if (sl < CAND) scand[(t0 + 16) * CAND + sl] = s0; }
                v = __fmaf_rn(-2.f, d1A[1] + d1B[1], cn1);
                if (v <= thr2) { int sl = atomicAdd(&scnt[t0 + 16], 1); if (sl < CAND) scand[(t0 + 16) * CAND + sl] = s0 + 1; }
                v = __fmaf_rn(-2.f, d1A[2] + d1B[2], cn0);
                if (v <= thr3) { int sl = atomicAdd(&scnt[t0 + 24], 1); if (sl < CAND) scand[(t0 + 24) * CAND + sl] = s0; }
                v = __fmaf_rn(-2.f, d1A[3] + d1B[3], cn1);
                if (v <= thr3) { int sl = atomicAdd(&scnt[t0 + 24], 1); if (sl < CAND) scand[(t0 + 24) * CAND + sl] = s0 + 1; }
            }
            __syncthreads();
        }
    }

    // ---- exact rescore (2 threads per token) ----
    {
        int t = tid & 127;
        int half = tid >> 7;
        float A = stn2[t];
        float bestd = 3.4e38f;
        int bests = 1 << 30;
        int cnt = scnt[t];
        if (cnt <= CAND) {
            for (int i = half; i < cnt; i += 2) {
                int s = scand[t * CAND + i];
                float d = rescore_one(tok, t, s, A, scn, codebook);
                if (d < bestd || (d == bestd && s < bests)) { bestd = d; bests = s; }
            }
        } else {
            for (int s = half; s < S; s += 2) {
                float d = rescore_one(tok, t, s, A, scn, codebook);
                if (d < bestd || (d == bestd && s < bests)) { bestd = d; bests = s; }
            }
        }
        pbv[tid] = bestd;
        pbi[tid] = bests;
    }
    __syncthreads();
    if (tid < TOK) {
        float d1 = pbv[tid];       int s1 = pbi[tid];
        float d2 = pbv[tid + 128]; int s2 = pbi[tid + 128];
        int bs = (d2 < d1 || (d2 == d1 && s2 < s1)) ? s2 : s1;
        sbi[tid] = bs;
        outp[OFF_IDX + (size_t)n * P + p0 + tid] = (float)bs;
        atomicAdd(&g_counts[bs], 1.0f);
    }
    __syncthreads();

    // gather xq into scr[c][t] (overwrites A/B tiles) + dw scatter
    {
        int t = tid >> 1, c0 = (tid & 1) * 32;
        int sdx = sbi[t];
        const float4* crow = (const float4*)(codebook + sdx * C + c0);
        #pragma unroll
        for (int q = 0; q < 8; q++) {
            float4 v = crow[q];
            int c = c0 + q * 4;
            scr[(c + 0) * TOK + t] = v.x;
            scr[(c + 1) * TOK + t] = v.y;
            scr[(c + 2) * TOK + t] = v.z;
            scr[(c + 3) * TOK + t] = v.w;
        }
        float* dwrow = g_dw + sdx * C + c0;
        #pragma unroll 8
        for (int j = 0; j < 32; j++)
            atomicAdd(&dwrow[j], tok[(c0 + j) * TOK + t]);
    }
    __syncthreads();

    // straight-through out + commitment loss
    float lsum = 0.f;
    float* ob = outp + OFF_OUT + (size_t)n * C * P + p0;
    for (int v = tid; v < C * TOK; v += TPB) {
        int c = v >> 7, t = v & 127;
        float xv = tok[c * TOK + t];
        float qv = scr[c * TOK + t];
        ob[c * P + t] = xv + (qv - xv);
        float dd = xv - qv;
        lsum = fmaf(dd, dd, lsum);
    }
    #pragma unroll
    for (int d = 16; d >= 1; d >>= 1) lsum += __shfl_xor_sync(0xffffffffu, lsum, d);
    if (lane == 0) sred[w] = lsum;
    __syncthreads();
    if (tid == 0) {
        float tot = 0.f;
        #pragma unroll
        for (int q = 0; q < TPB / 32; q++) tot += sred[q];
        atomicAdd(&g_loss, tot);
    }
}

// ---------------- finalize: 64 blocks, each redundantly reduces nsum ----------------
__global__ void vq_finalize_kernel(const float* __restrict__ ema_w,
                                   const float* __restrict__ cluster_size,
                                   const int* __restrict__ steps_p,
                                   float* __restrict__ outp) {
    __shared__ float sred[S];
    int t = threadIdx.x;          // 0..511

    int st = steps_p[0];
    if (st <= 0 || st > 1000000000) {
        float f = __int_as_float(st);
        st = (f > 0.5f && f < 1e9f) ? (int)(f + 0.5f) : 1;
    }
    float bias_corr = (float)(1.0 - pow(0.99, (double)st));

    float cs_new_t = 0.99f * cluster_size[t] + 0.01f * g_counts[t];
    float cs_bc_t  = cs_new_t / bias_corr;
    sred[t] = cs_bc_t;
    if (blockIdx.x == 0) outp[OFF_CS + t] = cs_new_t;
    __syncthreads();
    #pragma unroll
    for (int d = 256; d >= 1; d >>= 1) {
        if (t < d) sred[t] += sred[t + d];
        __syncthreads();
    }
    float nsum = sred[0];

    // this block's 8 codes x 64 channels
    int sc = blockIdx.x * 8 + (t >> 6);
    int c  = t & 63;
    float cs_bc_s = (0.99f * cluster_size[sc] + 0.01f * g_counts[sc]) / bias_corr;
    float upd = (cs_bc_s + 1e-7f) / (nsum + (float)S * 1e-7f) * nsum;
    int i = sc * C + c;
    float ew = 0.99f * ema_w[i] + 0.01f * g_dw[i];
    outp[OFF_EW + i]  = ew;
    outp[OFF_NCB + i] = (ew / bias_corr) / upd;

    if (blockIdx.x == 0 && t == 0) outp[OFF_LOSS] = g_loss / 8388608.0f;
}

// ---------------- launch ----------------
extern "C" void kernel_launch(void* const* d_in, const int* in_sizes, int n_in,
                              void* d_out, int out_size) {
    const float* x            = (const float*)d_in[0];
    const float* codebook     = (const float*)d_in[1];
    const float* ema_w        = (const float*)d_in[2];
    const float* cluster_size = (const float*)d_in[3];
    const int*   steps        = (const int*)d_in[4];
    float* outp = (float*)d_out;

    cudaFuncSetAttribute(vq_main_kernel,
                         cudaFuncAttributeMaxDynamicSharedMemorySize, SMEM_BYTES);

    vq_prep_kernel<<<64, 256>>>(codebook);
    vq_main_kernel<<<NTOK / TOK, TPB, SMEM_BYTES>>>(x, codebook, outp);
    vq_finalize_kernel<<<64, 512>>>(ema_w, cluster_size, steps, outp);
}